// round 10
// baseline (speedup 1.0000x reference)
#include <cuda_runtime.h>
#include <cstdint>
#include <cstddef>

#define N_NODES 20000
#define N_EDGES 320000
#define EPB 16

#define LOG2_C       0.6931471805599453f
#define INV_SQRT3_C  0.5773502691896258f
#define INV_SQRT8_C  0.35355339059327373f
#define W_SCALE      0.125f
#define INV_MUL_C    0.125f
#define SC_A_C       0.02209708691207961f   // 1/sqrt(128) * 1/sqrt(16)
#define SC_B_C       0.04419417382415922f   // 1/sqrt(512)

#define ROWS_S 20032
#define ROWS_V 60032

// scratch (__device__ globals). Referenced ONLY from device code.
__device__ __align__(1024) float d_sv[(size_t)N_NODES * 256];
__device__ __align__(1024) float d_cat_s[(size_t)ROWS_S * 640];
__device__ __align__(1024) float d_cat_v[(size_t)ROWS_V * 640];
__device__ __align__(1024) float d_Wcat_s[640 * 64];
__device__ __align__(1024) float d_Wcat_v[640 * 64];

__device__ __forceinline__ unsigned smem_u32(const void* p) {
    return (unsigned)__cvta_generic_to_shared(p);
}
__device__ __forceinline__ float4 ld4s(const float* p) {
    return *reinterpret_cast<const float4*>(p);
}
__device__ __forceinline__ void cp_async16(unsigned saddr, const void* gaddr) {
    asm volatile("cp.async.cg.shared.global [%0], [%1], 16;" :: "r"(saddr), "l"(gaddr));
}
__device__ __forceinline__ void cp_commit() {
    asm volatile("cp.async.commit_group;" ::: "memory");
}
template<int NWAIT>
__device__ __forceinline__ void cp_wait() {
    asm volatile("cp.async.wait_group %0;" :: "n"(NWAIT) : "memory");
}

// ---- packed fp32 (FFMA2) helpers --------------------------------------
__device__ __forceinline__ unsigned long long pack2(float v) {
    unsigned long long r;
    asm("mov.b64 %0, {%1, %1};" : "=l"(r) : "f"(v));
    return r;
}
__device__ __forceinline__ void ffma2(unsigned long long& d,
                                      unsigned long long a, unsigned long long b) {
    asm("fma.rn.f32x2 %0, %1, %2, %0;" : "+l"(d) : "l"(a), "l"(b));
}
__device__ __forceinline__ float2 unpack2(unsigned long long v) {
    float2 r;
    asm("mov.b64 {%0, %1}, %2;" : "=f"(r.x), "=f"(r.y) : "l"(v));
    return r;
}

// ---------------------------------------------------------------------------
__global__ void wfold_kernel(const float* __restrict__ W2s, const float* __restrict__ Wsc_s,
                             const float* __restrict__ W2v, const float* __restrict__ Wsc_v)
{
    const int i = blockIdx.x * blockDim.x + threadIdx.x;
    if (i < 8192) {
        d_Wcat_s[i] = W2s[i] * SC_A_C;
        d_Wcat_v[i] = W2v[i] * SC_A_C;
    } else if (i < 40960) {
        d_Wcat_s[i] = Wsc_s[i - 8192] * SC_B_C;
        d_Wcat_v[i] = Wsc_v[i - 8192] * SC_B_C;
    }
}

// ---------------------------------------------------------------------------
// node prep (unchanged)
// ---------------------------------------------------------------------------
__global__ void __launch_bounds__(256)
nodeprep_kernel(const float* __restrict__ node_feat,
                const float* __restrict__ node_attr,
                const float* __restrict__ W1s,
                const float* __restrict__ W1v)
{
    __shared__ float sW1s[4096];
    __shared__ float sW1v[4096];
    __shared__ float sNF[4][256];
    __shared__ float4 sAT[4][2];

    const int tid = threadIdx.x;
    for (int i = tid; i < 4096; i += 256) { sW1s[i] = W1s[i]; sW1v[i] = W1v[i]; }
    __syncthreads();

    const int ngroups = N_NODES / 4;
    for (int g = blockIdx.x; g < ngroups; g += gridDim.x) {
        const int n0 = g * 4;
        __syncthreads();
        for (int i = tid; i < 1024; i += 256) {
            const int nl = i >> 8, j = i & 255;
            sNF[nl][j] = node_feat[(size_t)(n0 + nl) * 256 + j];
        }
        if (tid < 8) {
            const int nl = tid >> 1, j = tid & 1;
            sAT[nl][j] = __ldg(reinterpret_cast<const float4*>(node_attr + (size_t)(n0 + nl) * 8) + j);
        }
        __syncthreads();

        {
            const int nl = tid >> 6, w = tid & 63;
            const int n = n0 + nl;
            float sacc = 0.f, v0a = 0.f, v1a = 0.f, v2a = 0.f;
#pragma unroll
            for (int u = 0; u < 64; ++u) {
                const float ws = sW1s[u * 64 + w];
                const float wvv = sW1v[u * 64 + w];
                sacc = fmaf(sNF[nl][u], ws, sacc);
                v0a  = fmaf(sNF[nl][64 + 3 * u + 0], wvv, v0a);
                v1a  = fmaf(sNF[nl][64 + 3 * u + 1], wvv, v1a);
                v2a  = fmaf(sNF[nl][64 + 3 * u + 2], wvv, v2a);
            }
            float* o = d_sv + (size_t)n * 256;
            o[w] = sacc * INV_MUL_C;
            o[64 + 3 * w + 0] = v0a * INV_MUL_C;
            o[64 + 3 * w + 1] = v1a * INV_MUL_C;
            o[64 + 3 * w + 2] = v2a * INV_MUL_C;
        }

        if (tid < 128) {
            const int nl = tid >> 5, u = tid & 31;
            reinterpret_cast<float4*>(d_cat_s + (size_t)(n0 + nl) * 640)[u] =
                make_float4(0.f, 0.f, 0.f, 0.f);
        }
        for (int i = tid; i < 384; i += 256) {
            const int rr = i >> 5, u = i & 31;
            const int nl = rr / 3, c = rr - 3 * nl;
            reinterpret_cast<float4*>(d_cat_v + ((size_t)(n0 + nl) * 3 + c) * 640)[u] =
                make_float4(0.f, 0.f, 0.f, 0.f);
        }

        for (int i = tid; i < 512; i += 256) {
            const int nl = i >> 7, p4 = i & 127;
            const float a = sNF[nl][p4 >> 1];
            const float4 at = sAT[nl][p4 & 1];
            reinterpret_cast<float4*>(d_cat_s + (size_t)(n0 + nl) * 640 + 128)[p4] =
                make_float4(a * at.x, a * at.y, a * at.z, a * at.w);
        }
        for (int i = tid; i < 1536; i += 256) {
            const int nl = i / 384;
            const int r  = i - nl * 384;
            const int c  = r >> 7, p4 = r & 127;
            const float a = sNF[nl][64 + 3 * (p4 >> 1) + c];
            const float4 at = sAT[nl][p4 & 1];
            reinterpret_cast<float4*>(d_cat_v + ((size_t)(n0 + nl) * 3 + c) * 640 + 128)[p4] =
                make_float4(a * at.x, a * at.y, a * at.z, a * at.w);
        }
    }
}

// ---------------------------------------------------------------------------
// edge kernel v3: EPB=16, prefetch, FFMA2 phase B (k-major sH, stride 20).
// dynamic smem (floats):
//   sOut  [0,16384)    2*16*512
//   sH    [16384,..)   64*20 = 1280   (k-major, 16B-aligned rows)
//   sWfc1 [17664,..)   512
//   sBas  [18176,..)   256
//   sShs  [18432,..)   128
//   sIdx  [18560,..)   64
// total 18624 floats = 74496 B -> 2 CTAs/SM
// ---------------------------------------------------------------------------
#define EDGE_SMEM (18624 * 4)

__global__ void __launch_bounds__(256, 2)
edge_kernel(const float* __restrict__ edge_sh,
            const float* __restrict__ edge_basis,
            const float* __restrict__ Wfc1,
            const float* __restrict__ Wfc2,
            const int*   __restrict__ edge_idx)
{
    extern __shared__ float esm[];
    float* sOut  = esm;
    float* sH    = esm + 16384;      // [64][20], only [..][0..15] used
    float* sWfc1 = esm + 17664;
    float* sBas  = esm + 18176;
    float* sShs  = esm + 18432;
    int*   sIdx  = (int*)(esm + 18560);

    const int tid = threadIdx.x;

    float wcol[64];
#pragma unroll
    for (int k = 0; k < 64; ++k) wcol[k] = Wfc2[k * 256 + tid] * W_SCALE;
    for (int i = tid; i < 512; i += 256) sWfc1[i] = Wfc1[i] * INV_SQRT8_C;

    const int niter = N_EDGES / EPB;   // 20000

    auto prefetch = [&](int buf, int it_tgt) {
        const size_t e0 = (size_t)it_tgt * EPB;
        if (tid < 32) {
            cp_async16(smem_u32(sBas + buf * 128 + tid * 4), edge_basis + e0 * 8 + tid * 4);
        } else if (tid < 48) {
            cp_async16(smem_u32(sShs + buf * 64 + (tid - 32) * 4), edge_sh + e0 * 4 + (tid - 32) * 4);
        } else if (tid < 56) {
            cp_async16(smem_u32(sIdx + buf * 32 + (tid - 48) * 4), edge_idx + e0 * 2 + (tid - 48) * 4);
        }
    };

    if (tid < 56) { prefetch(0, blockIdx.x); cp_commit(); cp_wait<0>(); }
    __syncthreads();

    int li = 0;
    for (int it = blockIdx.x; it < niter; it += gridDim.x, ++li) {
        const int cur = li & 1;

        if (tid < 4 * EPB) asm volatile("cp.async.bulk.wait_group 1;" ::: "memory");

        {
            const int nit = it + gridDim.x;
            if (tid < 56) {
                if (nit < niter) prefetch(cur ^ 1, nit);
                cp_commit();
            }
        }

        // phase A: h[k][q] (k-major) for 16 edges
#pragma unroll
        for (int i = tid; i < EPB * 64; i += 256) {
            const int el = i >> 6, k = i & 63;
            const float* bb = sBas + cur * 128 + el * 8;
            const float4 b0 = ld4s(bb);
            const float4 b1 = ld4s(bb + 4);
            float acc;
            acc = b0.x * sWfc1[0 * 64 + k];
            acc = fmaf(b0.y, sWfc1[1 * 64 + k], acc);
            acc = fmaf(b0.z, sWfc1[2 * 64 + k], acc);
            acc = fmaf(b0.w, sWfc1[3 * 64 + k], acc);
            acc = fmaf(b1.x, sWfc1[4 * 64 + k], acc);
            acc = fmaf(b1.y, sWfc1[5 * 64 + k], acc);
            acc = fmaf(b1.z, sWfc1[6 * 64 + k], acc);
            acc = fmaf(b1.w, sWfc1[7 * 64 + k], acc);
            const float t = __expf(-fabsf(acc));
            sH[k * 20 + el] = fmaxf(acc, 0.f) + __logf(1.f + t) - LOG2_C;
        }
        __syncthreads();

        // phase B: FFMA2 — wv2[j] holds edges (2j, 2j+1) for this thread's col
        unsigned long long wv2[8];
#pragma unroll
        for (int j = 0; j < 8; ++j) wv2[j] = 0ULL;
#pragma unroll 16
        for (int k = 0; k < 64; ++k) {
            const unsigned long long wpk = pack2(wcol[k]);
            const ulonglong2* hp = reinterpret_cast<const ulonglong2*>(sH + k * 20);
#pragma unroll
            for (int qp4 = 0; qp4 < 4; ++qp4) {
                const ulonglong2 h2 = hp[qp4];          // broadcast LDS.128
                ffma2(wv2[2 * qp4 + 0], h2.x, wpk);
                ffma2(wv2[2 * qp4 + 1], h2.y, wpk);
            }
        }
        float wv[EPB];
#pragma unroll
        for (int j = 0; j < 8; ++j) {
            const float2 u = unpack2(wv2[j]);
            wv[2 * j] = u.x; wv[2 * j + 1] = u.y;
        }

        // phase C: gather + tensor product -> staging smem
#pragma unroll
        for (int q = 0; q < EPB; ++q) {
            const float w = wv[q];
            const int src = sIdx[cur * 32 + 2 * q + 1];
            const float* nrow = d_sv + (size_t)src * 256;
            const float shx = sShs[cur * 64 + 4 * q + 0];
            const float shy = sShs[cur * 64 + 4 * q + 1];
            const float shz = sShs[cur * 64 + 4 * q + 2];
            const float shw = sShs[cur * 64 + 4 * q + 3];
            float* st = sOut + (cur * EPB + q) * 512;
            const int col = tid;
            if (col < 64) {
                st[col] = w * nrow[col] * shx;
            } else if (col < 128) {
                const int u = col - 64;
                const float b = w * nrow[u];
                st[128 + 0 * 128 + u] = b * shy;
                st[128 + 1 * 128 + u] = b * shz;
                st[128 + 2 * 128 + u] = b * shw;
            } else if (col < 192) {
                const int u = col - 128;
                const float ws = w * shx;
                st[128 + 0 * 128 + 64 + u] = ws * nrow[64 + 3 * u + 0];
                st[128 + 1 * 128 + 64 + u] = ws * nrow[64 + 3 * u + 1];
                st[128 + 2 * 128 + 64 + u] = ws * nrow[64 + 3 * u + 2];
            } else {
                const int u = col - 192;
                const float x0 = nrow[64 + 3 * u + 0];
                const float x1 = nrow[64 + 3 * u + 1];
                const float x2 = nrow[64 + 3 * u + 2];
                st[64 + u] = w * INV_SQRT3_C * (x0 * shy + x1 * shz + x2 * shw);
            }
        }

        if (tid < 56) cp_wait<0>();
        __syncthreads();

        if (tid < 4 * EPB) {
            asm volatile("fence.proxy.async.shared::cta;" ::: "memory");
            const int q = tid >> 2, part = tid & 3;
            const int dst = sIdx[cur * 32 + 2 * q];
            float* g = (part == 0)
                     ? (d_cat_s + (size_t)dst * 640)
                     : (d_cat_v + ((size_t)dst * 3 + (part - 1)) * 640);
            const unsigned saddr = smem_u32(sOut + (cur * EPB + q) * 512 + part * 128);
            asm volatile(
                "cp.reduce.async.bulk.global.shared::cta.bulk_group.add.f32 [%0], [%1], %2;"
                :: "l"(g), "r"(saddr), "n"(512) : "memory");
            asm volatile("cp.async.bulk.commit_group;" ::: "memory");
        }
    }
    if (tid < 4 * EPB) asm volatile("cp.async.bulk.wait_group 0;" ::: "memory");
}

// ===========================================================================
// Pipelined register-tiled SGEMM with FFMA2 accumulators.
// ===========================================================================
#define KCH 80
#define PA 84
#define GEMM_SMEM ((2 * 64 * PA + 2 * KCH * 64) * 4)

template<int MODE>
__global__ void __launch_bounds__(256, 2)
out_gemm_kernel(float* __restrict__ out)
{
    const float* __restrict__ A = (MODE == 0) ? d_cat_s  : d_cat_v;
    const float* __restrict__ B = (MODE == 0) ? d_Wcat_s : d_Wcat_v;

    extern __shared__ float sm[];
    float* sA = sm;
    float* sB = sm + 2 * 64 * PA;

    const int tid = threadIdx.x;
    const int tx = tid & 15, ty = tid >> 4;
    const int r0 = blockIdx.x * 64;

    // acc2[r][p] = packed col-pair p (cols 4tx+2p, 4tx+2p+1) of row r
    unsigned long long acc2[4][2];
#pragma unroll
    for (int i = 0; i < 4; ++i) { acc2[i][0] = 0ULL; acc2[i][1] = 0ULL; }

    auto stage = [&](int buf, int c) {
        const int k0 = c * KCH;
        float* sAb = sA + buf * 64 * PA;
        float* sBb = sB + buf * KCH * 64;
#pragma unroll
        for (int j = 0; j < 5; ++j) {
            const int idx = tid + 256 * j;
            const int row = idx / 20, u = idx - row * 20;
            cp_async16(smem_u32(sAb + row * PA + 4 * u),
                       A + (size_t)(r0 + row) * 640 + k0 + 4 * u);
        }
#pragma unroll
        for (int j = 0; j < 5; ++j) {
            const int idx = tid + 256 * j;
            const int row = idx >> 4, u = idx & 15;
            cp_async16(smem_u32(sBb + row * 64 + 4 * u),
                       B + (size_t)(k0 + row) * 64 + 4 * u);
        }
        cp_commit();
    };

    stage(0, 0);

#pragma unroll 1
    for (int c = 0; c < 8; ++c) {
        if (c < 7) { stage((c + 1) & 1, c + 1); cp_wait<1>(); }
        else       { cp_wait<0>(); }
        __syncthreads();

        const float* pa = sA + (c & 1) * 64 * PA + (4 * ty) * PA;
        const float* pb = sB + (c & 1) * KCH * 64 + 4 * tx;
#pragma unroll 4
        for (int k4 = 0; k4 < KCH / 4; ++k4) {
            const float4 a0 = ld4s(pa + 0 * PA + 4 * k4);
            const float4 a1 = ld4s(pa + 1 * PA + 4 * k4);
            const float4 a2 = ld4s(pa + 2 * PA + 4 * k4);
            const float4 a3 = ld4s(pa + 3 * PA + 4 * k4);
            const ulonglong2 b0 = *reinterpret_cast<const ulonglong2*>(pb + (4 * k4 + 0) * 64);
            const ulonglong2 b1 = *reinterpret_cast<const ulonglong2*>(pb + (4 * k4 + 1) * 64);
            const ulonglong2 b2 = *reinterpret_cast<const ulonglong2*>(pb + (4 * k4 + 2) * 64);
            const ulonglong2 b3 = *reinterpret_cast<const ulonglong2*>(pb + (4 * k4 + 3) * 64);

#define GSTEP(av0, av1, av2, av3, bq)                                          \
            {                                                                  \
                const unsigned long long p0 = pack2(av0);                      \
                const unsigned long long p1 = pack2(av1);                      \
                const unsigned long long p2 = pack2(av2);                      \
                const unsigned long long p3 = pack2(av3);                      \
                ffma2(acc2[0][0], p0, bq.x); ffma2(acc2[0][1], p0, bq.y);      \
                ffma2(acc2[1][0], p1, bq.x); ffma2(acc2[1][1], p1, bq.y);      \
                ffma2(acc2[2][0], p2, bq.x); ffma2(acc2[2][1], p2, bq.y);      \
                ffma2(acc2[3][0], p3, bq.x); ffma2(acc2[3][1], p3, bq.y);      \
            }
            GSTEP(a0.x, a1.x, a2.x, a3.x, b0)
            GSTEP(a0.y, a1.y, a2.y, a3.y, b1)
            GSTEP(a0.z, a1.z, a2.z, a3.z, b2)
            GSTEP(a0.w, a1.w, a2.w, a3.w, b3)
#undef GSTEP
        }
        __syncthreads();
    }

#pragma unroll
    for (int r = 0; r < 4; ++r) {
        const int grow = r0 + 4 * ty + r;
        const float2 c0 = unpack2(acc2[r][0]);
        const float2 c1 = unpack2(acc2[r][1]);
        if (MODE == 0) {
            if (grow < N_NODES) {
                *reinterpret_cast<float4*>(out + (size_t)grow * 256 + 4 * tx) =
                    make_float4(c0.x, c0.y, c1.x, c1.y);
            }
        } else {
            if (grow < 3 * N_NODES) {
                const int n = grow / 3, cc = grow - 3 * (grow / 3);
                float* o = out + (size_t)n * 256 + 64 + cc;
                o[3 * (4 * tx + 0)] = c0.x;
                o[3 * (4 * tx + 1)] = c0.y;
                o[3 * (4 * tx + 2)] = c1.x;
                o[3 * (4 * tx + 3)] = c1.y;
            }
        }
    }
}

// ---------------------------------------------------------------------------
extern "C" void kernel_launch(void* const* d_in, const int* /*in_sizes*/, int /*n_in*/,
                              void* d_out, int /*out_size*/)
{
    const float* node_feat  = (const float*)d_in[0];
    const float* node_attr  = (const float*)d_in[1];
    const float* edge_sh    = (const float*)d_in[2];
    const float* edge_basis = (const float*)d_in[3];
    const float* W1s        = (const float*)d_in[4];
    const float* W1v        = (const float*)d_in[5];
    const float* Wfc1       = (const float*)d_in[6];
    const float* Wfc2       = (const float*)d_in[7];
    const float* W2s        = (const float*)d_in[8];
    const float* W2v        = (const float*)d_in[9];
    const float* Wsc_s      = (const float*)d_in[10];
    const float* Wsc_v      = (const float*)d_in[11];
    const int*   edge_idx   = (const int*)d_in[12];
    float* out = (float*)d_out;

    cudaFuncSetAttribute(edge_kernel, cudaFuncAttributeMaxDynamicSharedMemorySize, EDGE_SMEM);
    cudaFuncSetAttribute(out_gemm_kernel<0>, cudaFuncAttributeMaxDynamicSharedMemorySize, GEMM_SMEM);
    cudaFuncSetAttribute(out_gemm_kernel<1>, cudaFuncAttributeMaxDynamicSharedMemorySize, GEMM_SMEM);

    wfold_kernel<<<160, 256>>>(W2s, Wsc_s, W2v, Wsc_v);
    nodeprep_kernel<<<296, 256>>>(node_feat, node_attr, W1s, W1v);
    edge_kernel<<<296, 256, EDGE_SMEM>>>(edge_sh, edge_basis, Wfc1, Wfc2, edge_idx);

    out_gemm_kernel<0><<<ROWS_S / 64, 256, GEMM_SMEM>>>(out);
    out_gemm_kernel<1><<<ROWS_V / 64, 256, GEMM_SMEM>>>(out);
}

// round 11
// speedup vs baseline: 1.3964x; 1.3964x over previous
#include <cuda_runtime.h>
#include <cstdint>
#include <cstddef>

#define N_NODES 20000
#define N_EDGES 320000
#define EPB 16

#define LOG2_C       0.6931471805599453f
#define INV_SQRT3_C  0.5773502691896258f
#define INV_SQRT8_C  0.35355339059327373f
#define W_SCALE      0.125f
#define INV_MUL_C    0.125f
#define SC_A_C       0.02209708691207961f   // 1/sqrt(128) * 1/sqrt(16)
#define SC_B_C       0.04419417382415922f   // 1/sqrt(512)

#define ROWS_S 20032
#define ROWS_V 60032

// scratch (__device__ globals). Referenced ONLY from device code.
__device__ __align__(1024) float d_sv[(size_t)N_NODES * 256];
__device__ __align__(1024) float d_cat_s[(size_t)ROWS_S * 640];
__device__ __align__(1024) float d_cat_v[(size_t)ROWS_V * 640];
__device__ __align__(1024) float d_Wcat_s[640 * 64];
__device__ __align__(1024) float d_Wcat_v[640 * 64];

__device__ __forceinline__ unsigned smem_u32(const void* p) {
    return (unsigned)__cvta_generic_to_shared(p);
}
__device__ __forceinline__ float4 ld4s(const float* p) {
    return *reinterpret_cast<const float4*>(p);
}
__device__ __forceinline__ void cp_async16(unsigned saddr, const void* gaddr) {
    asm volatile("cp.async.cg.shared.global [%0], [%1], 16;" :: "r"(saddr), "l"(gaddr));
}
__device__ __forceinline__ void cp_commit() {
    asm volatile("cp.async.commit_group;" ::: "memory");
}
template<int NWAIT>
__device__ __forceinline__ void cp_wait() {
    asm volatile("cp.async.wait_group %0;" :: "n"(NWAIT) : "memory");
}

// ---- tf32 helpers ------------------------------------------------------
__device__ __forceinline__ unsigned f2tf32(float f) {
    unsigned r;
    asm("cvt.rna.tf32.f32 %0, %1;" : "=r"(r) : "f"(f));
    return r;
}
__device__ __forceinline__ void mma_tf32(float& c0, float& c1, float& c2, float& c3,
                                         unsigned a0, unsigned a1, unsigned a2, unsigned a3,
                                         unsigned b0, unsigned b1) {
    asm volatile(
        "mma.sync.aligned.m16n8k8.row.col.f32.tf32.tf32.f32 "
        "{%0,%1,%2,%3}, {%4,%5,%6,%7}, {%8,%9}, {%0,%1,%2,%3};"
        : "+f"(c0), "+f"(c1), "+f"(c2), "+f"(c3)
        : "r"(a0), "r"(a1), "r"(a2), "r"(a3), "r"(b0), "r"(b1));
}

// ---------------------------------------------------------------------------
__global__ void wfold_kernel(const float* __restrict__ W2s, const float* __restrict__ Wsc_s,
                             const float* __restrict__ W2v, const float* __restrict__ Wsc_v)
{
    const int i = blockIdx.x * blockDim.x + threadIdx.x;
    if (i < 8192) {
        d_Wcat_s[i] = W2s[i] * SC_A_C;
        d_Wcat_v[i] = W2v[i] * SC_A_C;
    } else if (i < 40960) {
        d_Wcat_s[i] = Wsc_s[i - 8192] * SC_B_C;
        d_Wcat_v[i] = Wsc_v[i - 8192] * SC_B_C;
    }
}

// ---------------------------------------------------------------------------
// node prep (unchanged)
// ---------------------------------------------------------------------------
__global__ void __launch_bounds__(256)
nodeprep_kernel(const float* __restrict__ node_feat,
                const float* __restrict__ node_attr,
                const float* __restrict__ W1s,
                const float* __restrict__ W1v)
{
    __shared__ float sW1s[4096];
    __shared__ float sW1v[4096];
    __shared__ float sNF[4][256];
    __shared__ float4 sAT[4][2];

    const int tid = threadIdx.x;
    for (int i = tid; i < 4096; i += 256) { sW1s[i] = W1s[i]; sW1v[i] = W1v[i]; }
    __syncthreads();

    const int ngroups = N_NODES / 4;
    for (int g = blockIdx.x; g < ngroups; g += gridDim.x) {
        const int n0 = g * 4;
        __syncthreads();
        for (int i = tid; i < 1024; i += 256) {
            const int nl = i >> 8, j = i & 255;
            sNF[nl][j] = node_feat[(size_t)(n0 + nl) * 256 + j];
        }
        if (tid < 8) {
            const int nl = tid >> 1, j = tid & 1;
            sAT[nl][j] = __ldg(reinterpret_cast<const float4*>(node_attr + (size_t)(n0 + nl) * 8) + j);
        }
        __syncthreads();

        {
            const int nl = tid >> 6, w = tid & 63;
            const int n = n0 + nl;
            float sacc = 0.f, v0a = 0.f, v1a = 0.f, v2a = 0.f;
#pragma unroll
            for (int u = 0; u < 64; ++u) {
                const float ws = sW1s[u * 64 + w];
                const float wvv = sW1v[u * 64 + w];
                sacc = fmaf(sNF[nl][u], ws, sacc);
                v0a  = fmaf(sNF[nl][64 + 3 * u + 0], wvv, v0a);
                v1a  = fmaf(sNF[nl][64 + 3 * u + 1], wvv, v1a);
                v2a  = fmaf(sNF[nl][64 + 3 * u + 2], wvv, v2a);
            }
            float* o = d_sv + (size_t)n * 256;
            o[w] = sacc * INV_MUL_C;
            o[64 + 3 * w + 0] = v0a * INV_MUL_C;
            o[64 + 3 * w + 1] = v1a * INV_MUL_C;
            o[64 + 3 * w + 2] = v2a * INV_MUL_C;
        }

        if (tid < 128) {
            const int nl = tid >> 5, u = tid & 31;
            reinterpret_cast<float4*>(d_cat_s + (size_t)(n0 + nl) * 640)[u] =
                make_float4(0.f, 0.f, 0.f, 0.f);
        }
        for (int i = tid; i < 384; i += 256) {
            const int rr = i >> 5, u = i & 31;
            const int nl = rr / 3, c = rr - 3 * nl;
            reinterpret_cast<float4*>(d_cat_v + ((size_t)(n0 + nl) * 3 + c) * 640)[u] =
                make_float4(0.f, 0.f, 0.f, 0.f);
        }

        for (int i = tid; i < 512; i += 256) {
            const int nl = i >> 7, p4 = i & 127;
            const float a = sNF[nl][p4 >> 1];
            const float4 at = sAT[nl][p4 & 1];
            reinterpret_cast<float4*>(d_cat_s + (size_t)(n0 + nl) * 640 + 128)[p4] =
                make_float4(a * at.x, a * at.y, a * at.z, a * at.w);
        }
        for (int i = tid; i < 1536; i += 256) {
            const int nl = i / 384;
            const int r  = i - nl * 384;
            const int c  = r >> 7, p4 = r & 127;
            const float a = sNF[nl][64 + 3 * (p4 >> 1) + c];
            const float4 at = sAT[nl][p4 & 1];
            reinterpret_cast<float4*>(d_cat_v + ((size_t)(n0 + nl) * 3 + c) * 640 + 128)[p4] =
                make_float4(a * at.x, a * at.y, a * at.z, a * at.w);
        }
    }
}

// ---------------------------------------------------------------------------
// edge kernel v4: EPB=16, prefetch, phase B via mma.sync tf32 (m16n8k8).
// Warp w owns output cols [32w, 32w+32). Phase C consumes D fragments
// directly (region uniform per warp). sOut slot stride 516 (conflict pad).
// dynamic smem (floats):
//   sOut  [0,16512)     2*16*516
//   sH    [16512,..)    16*68 = 1088  (pad 68 -> conflict-free A-frag loads)
//   sWfc1 [17600,..)    512
//   sBas  [18112,..)    256
//   sShs  [18368,..)    128
//   sIdx  [18496,..)    64
// total 18560 floats = 74240 B -> 2 CTAs/SM (reg-limited anyway)
// ---------------------------------------------------------------------------
#define SOUT_STRIDE 516
#define EDGE_SMEM (18560 * 4)

__global__ void __launch_bounds__(256, 2)
edge_kernel(const float* __restrict__ edge_sh,
            const float* __restrict__ edge_basis,
            const float* __restrict__ Wfc1,
            const float* __restrict__ Wfc2,
            const int*   __restrict__ edge_idx)
{
    extern __shared__ float esm[];
    float*    sOut  = esm;
    float*    sH    = esm + 16512;
    unsigned* sHu   = reinterpret_cast<unsigned*>(sH);
    float*    sWfc1 = esm + 17600;
    float*    sBas  = esm + 18112;
    float*    sShs  = esm + 18368;
    int*      sIdx  = (int*)(esm + 18496);

    const int tid  = threadIdx.x;
    const int lane = tid & 31, warp = tid >> 5;
    const int g    = lane >> 2;          // fragment group (row)
    const int ctig = lane & 3;           // thread-in-group (col)
    const int n0   = warp * 32;          // warp's output-column base
    const int region = warp >> 1;        // 0:A 1:B 2:C 3:D

    // B fragments: Wfc2 (k-major [64][256]) col-slice for this warp, tf32.
    unsigned bfrag[8][4][2];
#pragma unroll
    for (int ks = 0; ks < 8; ++ks)
#pragma unroll
        for (int nb = 0; nb < 4; ++nb) {
            const int nn = n0 + nb * 8 + g;
            bfrag[ks][nb][0] = f2tf32(Wfc2[(ks * 8 + ctig    ) * 256 + nn] * W_SCALE);
            bfrag[ks][nb][1] = f2tf32(Wfc2[(ks * 8 + ctig + 4) * 256 + nn] * W_SCALE);
        }
    for (int i = tid; i < 512; i += 256) sWfc1[i] = Wfc1[i] * INV_SQRT8_C;

    const int niter = N_EDGES / EPB;   // 20000

    auto prefetch = [&](int buf, int it_tgt) {
        const size_t e0 = (size_t)it_tgt * EPB;
        if (tid < 32) {
            cp_async16(smem_u32(sBas + buf * 128 + tid * 4), edge_basis + e0 * 8 + tid * 4);
        } else if (tid < 48) {
            cp_async16(smem_u32(sShs + buf * 64 + (tid - 32) * 4), edge_sh + e0 * 4 + (tid - 32) * 4);
        } else if (tid < 56) {
            cp_async16(smem_u32(sIdx + buf * 32 + (tid - 48) * 4), edge_idx + e0 * 2 + (tid - 48) * 4);
        }
    };

    if (tid < 56) { prefetch(0, blockIdx.x); cp_commit(); cp_wait<0>(); }
    __syncthreads();

    int li = 0;
    for (int it = blockIdx.x; it < niter; it += gridDim.x, ++li) {
        const int cur = li & 1;

        if (tid < 4 * EPB) asm volatile("cp.async.bulk.wait_group 1;" ::: "memory");

        {
            const int nit = it + gridDim.x;
            if (tid < 56) {
                if (nit < niter) prefetch(cur ^ 1, nit);
                cp_commit();
            }
        }

        // phase A: h for 16 edges, tf32-rounded, edge-major rows (pad 68)
#pragma unroll
        for (int i = tid; i < EPB * 64; i += 256) {
            const int el = i >> 6, k = i & 63;
            const float* bb = sBas + cur * 128 + el * 8;
            const float4 b0 = ld4s(bb);
            const float4 b1 = ld4s(bb + 4);
            float acc;
            acc = b0.x * sWfc1[0 * 64 + k];
            acc = fmaf(b0.y, sWfc1[1 * 64 + k], acc);
            acc = fmaf(b0.z, sWfc1[2 * 64 + k], acc);
            acc = fmaf(b0.w, sWfc1[3 * 64 + k], acc);
            acc = fmaf(b1.x, sWfc1[4 * 64 + k], acc);
            acc = fmaf(b1.y, sWfc1[5 * 64 + k], acc);
            acc = fmaf(b1.z, sWfc1[6 * 64 + k], acc);
            acc = fmaf(b1.w, sWfc1[7 * 64 + k], acc);
            const float t = __expf(-fabsf(acc));
            const float h = fmaxf(acc, 0.f) + __logf(1.f + t) - LOG2_C;
            sHu[el * 68 + k] = f2tf32(h);
        }
        __syncthreads();

        // phase B: tensor-core FC2. acc[nb][0..3] = D fragment (m16n8).
        float acc[4][4];
#pragma unroll
        for (int nb = 0; nb < 4; ++nb)
#pragma unroll
            for (int j = 0; j < 4; ++j) acc[nb][j] = 0.f;

#pragma unroll
        for (int ks = 0; ks < 8; ++ks) {
            const unsigned a0 = sHu[ g      * 68 + ks * 8 + ctig    ];
            const unsigned a1 = sHu[(g + 8) * 68 + ks * 8 + ctig    ];
            const unsigned a2 = sHu[ g      * 68 + ks * 8 + ctig + 4];
            const unsigned a3 = sHu[(g + 8) * 68 + ks * 8 + ctig + 4];
#pragma unroll
            for (int nb = 0; nb < 4; ++nb)
                mma_tf32(acc[nb][0], acc[nb][1], acc[nb][2], acc[nb][3],
                         a0, a1, a2, a3, bfrag[ks][nb][0], bfrag[ks][nb][1]);
        }

        // phase C: consume fragments directly.
        // c0:(q=g,col) c1:(q=g,col+1) c2:(q=g+8,col) c3:(q=g+8,col+1)
        auto process = [&](float w, int q, int col) {
            const int src = sIdx[cur * 32 + 2 * q + 1];
            const float* nrow = d_sv + (size_t)src * 256;
            const float4 sh = *reinterpret_cast<const float4*>(sShs + cur * 64 + 4 * q);
            float* st = sOut + (cur * EPB + q) * SOUT_STRIDE;
            if (region == 0) {                    // outA
                st[col] = w * nrow[col] * sh.x;
            } else if (region == 1) {             // outB (m = u), c-major
                const int u = col - 64;
                const float b = w * nrow[u];
                st[128 + u]       = b * sh.y;
                st[256 + u]       = b * sh.z;
                st[384 + u]       = b * sh.w;
            } else if (region == 2) {             // outC (m = 64+u), c-major
                const int u = col - 128;
                const float ws = w * sh.x;
                st[128 + 64 + u]  = ws * nrow[64 + 3 * u + 0];
                st[256 + 64 + u]  = ws * nrow[64 + 3 * u + 1];
                st[384 + 64 + u]  = ws * nrow[64 + 3 * u + 2];
            } else {                              // outD
                const int u = col - 192;
                const float x0 = nrow[64 + 3 * u + 0];
                const float x1 = nrow[64 + 3 * u + 1];
                const float x2 = nrow[64 + 3 * u + 2];
                st[64 + u] = w * INV_SQRT3_C * (x0 * sh.y + x1 * sh.z + x2 * sh.w);
            }
        };
#pragma unroll
        for (int nb = 0; nb < 4; ++nb) {
            const int colb = n0 + nb * 8 + 2 * ctig;
            process(acc[nb][0], g,     colb);
            process(acc[nb][1], g,     colb + 1);
            process(acc[nb][2], g + 8, colb);
            process(acc[nb][3], g + 8, colb + 1);
        }

        if (tid < 56) cp_wait<0>();
        __syncthreads();

        if (tid < 4 * EPB) {
            asm volatile("fence.proxy.async.shared::cta;" ::: "memory");
            const int q = tid >> 2, part = tid & 3;
            const int dst = sIdx[cur * 32 + 2 * q];
            float* gp = (part == 0)
                      ? (d_cat_s + (size_t)dst * 640)
                      : (d_cat_v + ((size_t)dst * 3 + (part - 1)) * 640);
            const unsigned saddr = smem_u32(sOut + (cur * EPB + q) * SOUT_STRIDE + part * 128);
            asm volatile(
                "cp.reduce.async.bulk.global.shared::cta.bulk_group.add.f32 [%0], [%1], %2;"
                :: "l"(gp), "r"(saddr), "n"(512) : "memory");
            asm volatile("cp.async.bulk.commit_group;" ::: "memory");
        }
    }
    if (tid < 4 * EPB) asm volatile("cp.async.bulk.wait_group 0;" ::: "memory");
}

// ===========================================================================
// Pipelined register-tiled SGEMM (reverted to R9 plain-FFMA version)
// ===========================================================================
#define KCH 80
#define PA 84
#define GEMM_SMEM ((2 * 64 * PA + 2 * KCH * 64) * 4)

template<int MODE>
__global__ void __launch_bounds__(256, 2)
out_gemm_kernel(float* __restrict__ out)
{
    const float* __restrict__ A = (MODE == 0) ? d_cat_s  : d_cat_v;
    const float* __restrict__ B = (MODE == 0) ? d_Wcat_s : d_Wcat_v;

    extern __shared__ float sm[];
    float* sA = sm;
    float* sB = sm + 2 * 64 * PA;

    const int tid = threadIdx.x;
    const int tx = tid & 15, ty = tid >> 4;
    const int r0 = blockIdx.x * 64;

    float acc[4][4];
#pragma unroll
    for (int i = 0; i < 4; ++i)
#pragma unroll
        for (int j = 0; j < 4; ++j) acc[i][j] = 0.f;

    auto stage = [&](int buf, int c) {
        const int k0 = c * KCH;
        float* sAb = sA + buf * 64 * PA;
        float* sBb = sB + buf * KCH * 64;
#pragma unroll
        for (int j = 0; j < 5; ++j) {
            const int idx = tid + 256 * j;
            const int row = idx / 20, u = idx - row * 20;
            cp_async16(smem_u32(sAb + row * PA + 4 * u),
                       A + (size_t)(r0 + row) * 640 + k0 + 4 * u);
        }
#pragma unroll
        for (int j = 0; j < 5; ++j) {
            const int idx = tid + 256 * j;
            const int row = idx >> 4, u = idx & 15;
            cp_async16(smem_u32(sBb + row * 64 + 4 * u),
                       B + (size_t)(k0 + row) * 64 + 4 * u);
        }
        cp_commit();
    };

    stage(0, 0);

#pragma unroll 1
    for (int c = 0; c < 8; ++c) {
        if (c < 7) { stage((c + 1) & 1, c + 1); cp_wait<1>(); }
        else       { cp_wait<0>(); }
        __syncthreads();

        const float* pa = sA + (c & 1) * 64 * PA + (4 * ty) * PA;
        const float* pb = sB + (c & 1) * KCH * 64 + 4 * tx;
#pragma unroll 4
        for (int k4 = 0; k4 < KCH / 4; ++k4) {
            const float4 a0 = ld4s(pa + 0 * PA + 4 * k4);
            const float4 a1 = ld4s(pa + 1 * PA + 4 * k4);
            const float4 a2 = ld4s(pa + 2 * PA + 4 * k4);
            const float4 a3 = ld4s(pa + 3 * PA + 4 * k4);
            const float4 b0 = ld4s(pb + (4 * k4 + 0) * 64);
            const float4 b1 = ld4s(pb + (4 * k4 + 1) * 64);
            const float4 b2 = ld4s(pb + (4 * k4 + 2) * 64);
            const float4 b3 = ld4s(pb + (4 * k4 + 3) * 64);

            acc[0][0] = fmaf(a0.x, b0.x, acc[0][0]); acc[0][1] = fmaf(a0.x, b0.y, acc[0][1]);
            acc[0][2] = fmaf(a0.x, b0.z, acc[0][2]); acc[0][3] = fmaf(a0.x, b0.w, acc[0][3]);
            acc[1][0] = fmaf(a1.x, b0.x, acc[1][0]); acc[1][1] = fmaf(a1.x, b0.y, acc[1][1]);
            acc[1][2] = fmaf(a1.x, b0.z, acc[1][2]); acc[1][3] = fmaf(a1.x, b0.w, acc[1][3]);
            acc[2][0] = fmaf(a2.x, b0.x, acc[2][0]); acc[2][1] = fmaf(a2.x, b0.y, acc[2][1]);
            acc[2][2] = fmaf(a2.x, b0.z, acc[2][2]); acc[2][3] = fmaf(a2.x, b0.w, acc[2][3]);
            acc[3][0] = fmaf(a3.x, b0.x, acc[3][0]); acc[3][1] = fmaf(a3.x, b0.y, acc[3][1]);
            acc[3][2] = fmaf(a3.x, b0.z, acc[3][2]); acc[3][3] = fmaf(a3.x, b0.w, acc[3][3]);

            acc[0][0] = fmaf(a0.y, b1.x, acc[0][0]); acc[0][1] = fmaf(a0.y, b1.y, acc[0][1]);
            acc[0][2] = fmaf(a0.y, b1.z, acc[0][2]); acc[0][3] = fmaf(a0.y, b1.w, acc[0][3]);
            acc[1][0] = fmaf(a1.y, b1.x, acc[1][0]); acc[1][1] = fmaf(a1.y, b1.y, acc[1][1]);
            acc[1][2] = fmaf(a1.y, b1.z, acc[1][2]); acc[1][3] = fmaf(a1.y, b1.w, acc[1][3]);
            acc[2][0] = fmaf(a2.y, b1.x, acc[2][0]); acc[2][1] = fmaf(a2.y, b1.y, acc[2][1]);
            acc[2][2] = fmaf(a2.y, b1.z, acc[2][2]); acc[2][3] = fmaf(a2.y, b1.w, acc[2][3]);
            acc[3][0] = fmaf(a3.y, b1.x, acc[3][0]); acc[3][1] = fmaf(a3.y, b1.y, acc[3][1]);
            acc[3][2] = fmaf(a3.y, b1.z, acc[3][2]); acc[3][3] = fmaf(a3.y, b1.w, acc[3][3]);

            acc[0][0] = fmaf(a0.z, b2.x, acc[0][0]); acc[0][1] = fmaf(a0.z, b2.y, acc[0][1]);
            acc[0][2] = fmaf(a0.z, b2.z, acc[0][2]); acc[0][3] = fmaf(a0.z, b2.w, acc[0][3]);
            acc[1][0] = fmaf(a1.z, b2.x, acc[1][0]); acc[1][1] = fmaf(a1.z, b2.y, acc[1][1]);
            acc[1][2] = fmaf(a1.z, b2.z, acc[1][2]); acc[1][3] = fmaf(a1.z, b2.w, acc[1][3]);
            acc[2][0] = fmaf(a2.z, b2.x, acc[2][0]); acc[2][1] = fmaf(a2.z, b2.y, acc[2][1]);
            acc[2][2] = fmaf(a2.z, b2.z, acc[2][2]); acc[2][3] = fmaf(a2.z, b2.w, acc[2][3]);
            acc[3][0] = fmaf(a3.z, b2.x, acc[3][0]); acc[3][1] = fmaf(a3.z, b2.y, acc[3][1]);
            acc[3][2] = fmaf(a3.z, b2.z, acc[3][2]); acc[3][3] = fmaf(a3.z, b2.w, acc[3][3]);

            acc[0][0] = fmaf(a0.w, b3.x, acc[0][0]); acc[0][1] = fmaf(a0.w, b3.y, acc[0][1]);
            acc[0][2] = fmaf(a0.w, b3.z, acc[0][2]); acc[0][3] = fmaf(a0.w, b3.w, acc[0][3]);
            acc[1][0] = fmaf(a1.w, b3.x, acc[1][0]); acc[1][1] = fmaf(a1.w, b3.y, acc[1][1]);
            acc[1][2] = fmaf(a1.w, b3.z, acc[1][2]); acc[1][3] = fmaf(a1.w, b3.w, acc[1][3]);
            acc[2][0] = fmaf(a2.w, b3.x, acc[2][0]); acc[2][1] = fmaf(a2.w, b3.y, acc[2][1]);
            acc[2][2] = fmaf(a2.w, b3.z, acc[2][2]); acc[2][3] = fmaf(a2.w, b3.w, acc[2][3]);
            acc[3][0] = fmaf(a3.w, b3.x, acc[3][0]); acc[3][1] = fmaf(a3.w, b3.y, acc[3][1]);
            acc[3][2] = fmaf(a3.w, b3.z, acc[3][2]); acc[3][3] = fmaf(a3.w, b3.w, acc[3][3]);
        }
        __syncthreads();
    }

#pragma unroll
    for (int r = 0; r < 4; ++r) {
        const int grow = r0 + 4 * ty + r;
        if (MODE == 0) {
            if (grow < N_NODES) {
                float4 v = make_float4(acc[r][0], acc[r][1], acc[r][2], acc[r][3]);
                *reinterpret_cast<float4*>(out + (size_t)grow * 256 + 4 * tx) = v;
            }
        } else {
            if (grow < 3 * N_NODES) {
                const int n = grow / 3, cc = grow - 3 * (grow / 3);
                float* o = out + (size_t)n * 256 + 64 + cc;
#pragma unroll
                for (int j = 0; j < 4; ++j) o[3 * (4 * tx + j)] = acc[r][j];
            }
        }
    }
}

// ---------------------------------------------------------------------------
extern "C" void kernel_launch(void* const* d_in, const int* /*in_sizes*/, int /*n_in*/,
                              void* d_out, int /*out_size*/)
{
    const float* node_feat  = (const float*)d_in[0];
    const float* node_attr  = (const float*)d_in[1];
    const float* edge_sh    = (const float*)d_in[2];
    const float* edge_basis = (const float*)d_in[3];
    const float* W1s        = (const float*)d_in[4];
    const float* W1v        = (const float*)d_in[5];
    const float* Wfc1       = (const float*)d_in[6];
    const float* Wfc2       = (const float*)d_in[7];
    const float* W2s        = (const float*)d_in[8];
    const float* W2v        = (const float*)d_in[9];
    const float* Wsc_s      = (const float*)d_in[10];
    const float* Wsc_v      = (const float*)d_in[11];
    const int*   edge_idx   = (const int*)d_in[12];
    float* out = (float*)d_out;

    cudaFuncSetAttribute(edge_kernel, cudaFuncAttributeMaxDynamicSharedMemorySize, EDGE_SMEM);
    cudaFuncSetAttribute(out_gemm_kernel<0>, cudaFuncAttributeMaxDynamicSharedMemorySize, GEMM_SMEM);
    cudaFuncSetAttribute(out_gemm_kernel<1>, cudaFuncAttributeMaxDynamicSharedMemorySize, GEMM_SMEM);

    wfold_kernel<<<160, 256>>>(W2s, Wsc_s, W2v, Wsc_v);
    nodeprep_kernel<<<296, 256>>>(node_feat, node_attr, W1s, W1v);
    edge_kernel<<<296, 256, EDGE_SMEM>>>(edge_sh, edge_basis, Wfc1, Wfc2, edge_idx);

    out_gemm_kernel<0><<<ROWS_S / 64, 256, GEMM_SMEM>>>(out);
    out_gemm_kernel<1><<<ROWS_V / 64, 256, GEMM_SMEM>>>(out);
}

// round 12
// speedup vs baseline: 1.6913x; 1.2112x over previous
#include <cuda_runtime.h>
#include <cstdint>
#include <cstddef>

#define N_NODES 20000
#define N_EDGES 320000
#define EPB 16

#define LOG2_C       0.6931471805599453f
#define INV_SQRT3_C  0.5773502691896258f
#define INV_SQRT8_C  0.35355339059327373f
#define W_SCALE      0.125f
#define INV_MUL_C    0.125f
#define SC_A_C       0.02209708691207961f   // 1/sqrt(128) * 1/sqrt(16)
#define SC_B_C       0.04419417382415922f   // 1/sqrt(512)

#define ROWS_S 20032
#define ROWS_V 60032
#define TILES_S 313
#define TILES_V 938

// scratch (__device__ globals). Referenced ONLY from device code.
__device__ __align__(1024) float d_sv[(size_t)N_NODES * 256];
__device__ __align__(1024) float d_cat_s[(size_t)ROWS_S * 640];
__device__ __align__(1024) float d_cat_v[(size_t)ROWS_V * 640];
__device__ __align__(1024) float d_WcatT_s[64 * 640];   // n-major, tf32 bits
__device__ __align__(1024) float d_WcatT_v[64 * 640];   // n-major, tf32 bits

__device__ __forceinline__ unsigned smem_u32(const void* p) {
    return (unsigned)__cvta_generic_to_shared(p);
}
__device__ __forceinline__ float4 ld4s(const float* p) {
    return *reinterpret_cast<const float4*>(p);
}
__device__ __forceinline__ void cp_async16(unsigned saddr, const void* gaddr) {
    asm volatile("cp.async.cg.shared.global [%0], [%1], 16;" :: "r"(saddr), "l"(gaddr));
}
__device__ __forceinline__ void cp_commit() {
    asm volatile("cp.async.commit_group;" ::: "memory");
}
template<int NWAIT>
__device__ __forceinline__ void cp_wait() {
    asm volatile("cp.async.wait_group %0;" :: "n"(NWAIT) : "memory");
}

// ---- tf32 helpers ------------------------------------------------------
__device__ __forceinline__ unsigned f2tf32(float f) {
    unsigned r;
    asm("cvt.rna.tf32.f32 %0, %1;" : "=r"(r) : "f"(f));
    return r;
}
__device__ __forceinline__ void mma_tf32(float& c0, float& c1, float& c2, float& c3,
                                         unsigned a0, unsigned a1, unsigned a2, unsigned a3,
                                         unsigned b0, unsigned b1) {
    asm volatile(
        "mma.sync.aligned.m16n8k8.row.col.f32.tf32.tf32.f32 "
        "{%0,%1,%2,%3}, {%4,%5,%6,%7}, {%8,%9}, {%0,%1,%2,%3};"
        : "+f"(c0), "+f"(c1), "+f"(c2), "+f"(c3)
        : "r"(a0), "r"(a1), "r"(a2), "r"(a3), "r"(b0), "r"(b1));
}

// ---------------------------------------------------------------------------
// wfold: WcatT[n][k] = tf32( scale * W[k][n] ), n-major with scales folded
// ---------------------------------------------------------------------------
__global__ void wfold_kernel(const float* __restrict__ W2s, const float* __restrict__ Wsc_s,
                             const float* __restrict__ W2v, const float* __restrict__ Wsc_v)
{
    const int i = blockIdx.x * blockDim.x + threadIdx.x;   // over 40960
    if (i >= 40960) return;
    const int n = i / 640, k = i - n * 640;
    const float vs = (k < 128) ? W2s[k * 64 + n] * SC_A_C : Wsc_s[(k - 128) * 64 + n] * SC_B_C;
    const float vv = (k < 128) ? W2v[k * 64 + n] * SC_A_C : Wsc_v[(k - 128) * 64 + n] * SC_B_C;
    d_WcatT_s[i] = __uint_as_float(f2tf32(vs));
    d_WcatT_v[i] = __uint_as_float(f2tf32(vv));
}

// ---------------------------------------------------------------------------
// node prep (unchanged)
// ---------------------------------------------------------------------------
__global__ void __launch_bounds__(256)
nodeprep_kernel(const float* __restrict__ node_feat,
                const float* __restrict__ node_attr,
                const float* __restrict__ W1s,
                const float* __restrict__ W1v)
{
    __shared__ float sW1s[4096];
    __shared__ float sW1v[4096];
    __shared__ float sNF[4][256];
    __shared__ float4 sAT[4][2];

    const int tid = threadIdx.x;
    for (int i = tid; i < 4096; i += 256) { sW1s[i] = W1s[i]; sW1v[i] = W1v[i]; }
    __syncthreads();

    const int ngroups = N_NODES / 4;
    for (int g = blockIdx.x; g < ngroups; g += gridDim.x) {
        const int n0 = g * 4;
        __syncthreads();
        for (int i = tid; i < 1024; i += 256) {
            const int nl = i >> 8, j = i & 255;
            sNF[nl][j] = node_feat[(size_t)(n0 + nl) * 256 + j];
        }
        if (tid < 8) {
            const int nl = tid >> 1, j = tid & 1;
            sAT[nl][j] = __ldg(reinterpret_cast<const float4*>(node_attr + (size_t)(n0 + nl) * 8) + j);
        }
        __syncthreads();

        {
            const int nl = tid >> 6, w = tid & 63;
            const int n = n0 + nl;
            float sacc = 0.f, v0a = 0.f, v1a = 0.f, v2a = 0.f;
#pragma unroll
            for (int u = 0; u < 64; ++u) {
                const float ws = sW1s[u * 64 + w];
                const float wvv = sW1v[u * 64 + w];
                sacc = fmaf(sNF[nl][u], ws, sacc);
                v0a  = fmaf(sNF[nl][64 + 3 * u + 0], wvv, v0a);
                v1a  = fmaf(sNF[nl][64 + 3 * u + 1], wvv, v1a);
                v2a  = fmaf(sNF[nl][64 + 3 * u + 2], wvv, v2a);
            }
            float* o = d_sv + (size_t)n * 256;
            o[w] = sacc * INV_MUL_C;
            o[64 + 3 * w + 0] = v0a * INV_MUL_C;
            o[64 + 3 * w + 1] = v1a * INV_MUL_C;
            o[64 + 3 * w + 2] = v2a * INV_MUL_C;
        }

        if (tid < 128) {
            const int nl = tid >> 5, u = tid & 31;
            reinterpret_cast<float4*>(d_cat_s + (size_t)(n0 + nl) * 640)[u] =
                make_float4(0.f, 0.f, 0.f, 0.f);
        }
        for (int i = tid; i < 384; i += 256) {
            const int rr = i >> 5, u = i & 31;
            const int nl = rr / 3, c = rr - 3 * nl;
            reinterpret_cast<float4*>(d_cat_v + ((size_t)(n0 + nl) * 3 + c) * 640)[u] =
                make_float4(0.f, 0.f, 0.f, 0.f);
        }

        for (int i = tid; i < 512; i += 256) {
            const int nl = i >> 7, p4 = i & 127;
            const float a = sNF[nl][p4 >> 1];
            const float4 at = sAT[nl][p4 & 1];
            reinterpret_cast<float4*>(d_cat_s + (size_t)(n0 + nl) * 640 + 128)[p4] =
                make_float4(a * at.x, a * at.y, a * at.z, a * at.w);
        }
        for (int i = tid; i < 1536; i += 256) {
            const int nl = i / 384;
            const int r  = i - nl * 384;
            const int c  = r >> 7, p4 = r & 127;
            const float a = sNF[nl][64 + 3 * (p4 >> 1) + c];
            const float4 at = sAT[nl][p4 & 1];
            reinterpret_cast<float4*>(d_cat_v + ((size_t)(n0 + nl) * 3 + c) * 640 + 128)[p4] =
                make_float4(a * at.x, a * at.y, a * at.z, a * at.w);
        }
    }
}

// ---------------------------------------------------------------------------
// edge kernel (unchanged from R11 — tf32 mma FC2, EPB=16, prefetch)
// ---------------------------------------------------------------------------
#define SOUT_STRIDE 516
#define EDGE_SMEM (18560 * 4)

__global__ void __launch_bounds__(256, 2)
edge_kernel(const float* __restrict__ edge_sh,
            const float* __restrict__ edge_basis,
            const float* __restrict__ Wfc1,
            const float* __restrict__ Wfc2,
            const int*   __restrict__ edge_idx)
{
    extern __shared__ float esm[];
    float*    sOut  = esm;
    float*    sH    = esm + 16512;
    unsigned* sHu   = reinterpret_cast<unsigned*>(sH);
    float*    sWfc1 = esm + 17600;
    float*    sBas  = esm + 18112;
    float*    sShs  = esm + 18368;
    int*      sIdx  = (int*)(esm + 18496);

    const int tid  = threadIdx.x;
    const int lane = tid & 31, warp = tid >> 5;
    const int g    = lane >> 2;
    const int ctig = lane & 3;
    const int n0   = warp * 32;
    const int region = warp >> 1;

    unsigned bfrag[8][4][2];
#pragma unroll
    for (int ks = 0; ks < 8; ++ks)
#pragma unroll
        for (int nb = 0; nb < 4; ++nb) {
            const int nn = n0 + nb * 8 + g;
            bfrag[ks][nb][0] = f2tf32(Wfc2[(ks * 8 + ctig    ) * 256 + nn] * W_SCALE);
            bfrag[ks][nb][1] = f2tf32(Wfc2[(ks * 8 + ctig + 4) * 256 + nn] * W_SCALE);
        }
    for (int i = tid; i < 512; i += 256) sWfc1[i] = Wfc1[i] * INV_SQRT8_C;

    const int niter = N_EDGES / EPB;

    auto prefetch = [&](int buf, int it_tgt) {
        const size_t e0 = (size_t)it_tgt * EPB;
        if (tid < 32) {
            cp_async16(smem_u32(sBas + buf * 128 + tid * 4), edge_basis + e0 * 8 + tid * 4);
        } else if (tid < 48) {
            cp_async16(smem_u32(sShs + buf * 64 + (tid - 32) * 4), edge_sh + e0 * 4 + (tid - 32) * 4);
        } else if (tid < 56) {
            cp_async16(smem_u32(sIdx + buf * 32 + (tid - 48) * 4), edge_idx + e0 * 2 + (tid - 48) * 4);
        }
    };

    if (tid < 56) { prefetch(0, blockIdx.x); cp_commit(); cp_wait<0>(); }
    __syncthreads();

    int li = 0;
    for (int it = blockIdx.x; it < niter; it += gridDim.x, ++li) {
        const int cur = li & 1;

        if (tid < 4 * EPB) asm volatile("cp.async.bulk.wait_group 1;" ::: "memory");

        {
            const int nit = it + gridDim.x;
            if (tid < 56) {
                if (nit < niter) prefetch(cur ^ 1, nit);
                cp_commit();
            }
        }

#pragma unroll
        for (int i = tid; i < EPB * 64; i += 256) {
            const int el = i >> 6, k = i & 63;
            const float* bb = sBas + cur * 128 + el * 8;
            const float4 b0 = ld4s(bb);
            const float4 b1 = ld4s(bb + 4);
            float acc;
            acc = b0.x * sWfc1[0 * 64 + k];
            acc = fmaf(b0.y, sWfc1[1 * 64 + k], acc);
            acc = fmaf(b0.z, sWfc1[2 * 64 + k], acc);
            acc = fmaf(b0.w, sWfc1[3 * 64 + k], acc);
            acc = fmaf(b1.x, sWfc1[4 * 64 + k], acc);
            acc = fmaf(b1.y, sWfc1[5 * 64 + k], acc);
            acc = fmaf(b1.z, sWfc1[6 * 64 + k], acc);
            acc = fmaf(b1.w, sWfc1[7 * 64 + k], acc);
            const float t = __expf(-fabsf(acc));
            const float h = fmaxf(acc, 0.f) + __logf(1.f + t) - LOG2_C;
            sHu[el * 68 + k] = f2tf32(h);
        }
        __syncthreads();

        float acc[4][4];
#pragma unroll
        for (int nb = 0; nb < 4; ++nb)
#pragma unroll
            for (int j = 0; j < 4; ++j) acc[nb][j] = 0.f;

#pragma unroll
        for (int ks = 0; ks < 8; ++ks) {
            const unsigned a0 = sHu[ g      * 68 + ks * 8 + ctig    ];
            const unsigned a1 = sHu[(g + 8) * 68 + ks * 8 + ctig    ];
            const unsigned a2 = sHu[ g      * 68 + ks * 8 + ctig + 4];
            const unsigned a3 = sHu[(g + 8) * 68 + ks * 8 + ctig + 4];
#pragma unroll
            for (int nb = 0; nb < 4; ++nb)
                mma_tf32(acc[nb][0], acc[nb][1], acc[nb][2], acc[nb][3],
                         a0, a1, a2, a3, bfrag[ks][nb][0], bfrag[ks][nb][1]);
        }

        auto process = [&](float w, int q, int col) {
            const int src = sIdx[cur * 32 + 2 * q + 1];
            const float* nrow = d_sv + (size_t)src * 256;
            const float4 sh = *reinterpret_cast<const float4*>(sShs + cur * 64 + 4 * q);
            float* st = sOut + (cur * EPB + q) * SOUT_STRIDE;
            if (region == 0) {
                st[col] = w * nrow[col] * sh.x;
            } else if (region == 1) {
                const int u = col - 64;
                const float b = w * nrow[u];
                st[128 + u] = b * sh.y;
                st[256 + u] = b * sh.z;
                st[384 + u] = b * sh.w;
            } else if (region == 2) {
                const int u = col - 128;
                const float ws = w * sh.x;
                st[128 + 64 + u] = ws * nrow[64 + 3 * u + 0];
                st[256 + 64 + u] = ws * nrow[64 + 3 * u + 1];
                st[384 + 64 + u] = ws * nrow[64 + 3 * u + 2];
            } else {
                const int u = col - 192;
                const float x0 = nrow[64 + 3 * u + 0];
                const float x1 = nrow[64 + 3 * u + 1];
                const float x2 = nrow[64 + 3 * u + 2];
                st[64 + u] = w * INV_SQRT3_C * (x0 * sh.y + x1 * sh.z + x2 * sh.w);
            }
        };
#pragma unroll
        for (int nb = 0; nb < 4; ++nb) {
            const int colb = n0 + nb * 8 + 2 * ctig;
            process(acc[nb][0], g,     colb);
            process(acc[nb][1], g,     colb + 1);
            process(acc[nb][2], g + 8, colb);
            process(acc[nb][3], g + 8, colb + 1);
        }

        if (tid < 56) cp_wait<0>();
        __syncthreads();

        if (tid < 4 * EPB) {
            asm volatile("fence.proxy.async.shared::cta;" ::: "memory");
            const int q = tid >> 2, part = tid & 3;
            const int dst = sIdx[cur * 32 + 2 * q];
            float* gp = (part == 0)
                      ? (d_cat_s + (size_t)dst * 640)
                      : (d_cat_v + ((size_t)dst * 3 + (part - 1)) * 640);
            const unsigned saddr = smem_u32(sOut + (cur * EPB + q) * SOUT_STRIDE + part * 128);
            asm volatile(
                "cp.reduce.async.bulk.global.shared::cta.bulk_group.add.f32 [%0], [%1], %2;"
                :: "l"(gp), "r"(saddr), "n"(512) : "memory");
            asm volatile("cp.async.bulk.commit_group;" ::: "memory");
        }
    }
    if (tid < 4 * EPB) asm volatile("cp.async.bulk.wait_group 0;" ::: "memory");
}

// ===========================================================================
// Unified tf32 tensor-core out-GEMM: C[64x64] = A[rows][640] @ B[640][64].
// One launch covers both modes (blockIdx < TILES_S -> mode 0).
// Warp (warp&3) owns M-rows [16*(warp&3)..+16), (warp>>2) owns N-cols [32*..+32).
// A fp32 in smem (cvt at load), B pre-tf32 n-major in smem. Both tiles
// stride-84 padded -> all fragment LDS conflict-free.
// smem: sA[2][64*84] + sB[2][64*84] = 86016 B -> 2 CTAs/SM.
// ===========================================================================
#define KCH 80
#define PAD 84
#define GEMM_SMEM (4 * 64 * PAD * 4)

__global__ void __launch_bounds__(256, 2)
out_gemm_tc(float* __restrict__ out)
{
    const int bid  = blockIdx.x;
    const int mode = (bid >= TILES_S);
    const int tile = mode ? bid - TILES_S : bid;
    const float* __restrict__ A  = mode ? d_cat_v   : d_cat_s;
    const float* __restrict__ Bt = mode ? d_WcatT_v : d_WcatT_s;

    extern __shared__ float sm[];
    float* sA = sm;                    // [2][64*PAD]
    float* sB = sm + 2 * 64 * PAD;     // [2][64*PAD] (n-major)

    const int tid = threadIdx.x;
    const int lane = tid & 31, warp = tid >> 5;
    const int g = lane >> 2, ctig = lane & 3;
    const int m0 = (warp & 3) * 16;
    const int n0 = (warp >> 2) * 32;
    const int r0 = tile * 64;

    auto stage = [&](int buf, int c) {
        const int k0 = c * KCH;
        float* sAb = sA + buf * 64 * PAD;
        float* sBb = sB + buf * 64 * PAD;
#pragma unroll
        for (int j = 0; j < 5; ++j) {
            const int idx = tid + 256 * j;
            const int row = idx / 20, u = idx - row * 20;
            cp_async16(smem_u32(sAb + row * PAD + 4 * u),
                       A + (size_t)(r0 + row) * 640 + k0 + 4 * u);
            cp_async16(smem_u32(sBb + row * PAD + 4 * u),
                       Bt + (size_t)row * 640 + k0 + 4 * u);
        }
        cp_commit();
    };

    float acc[4][4];
#pragma unroll
    for (int nb = 0; nb < 4; ++nb)
#pragma unroll
        for (int j = 0; j < 4; ++j) acc[nb][j] = 0.f;

    stage(0, 0);

#pragma unroll 1
    for (int c = 0; c < 8; ++c) {
        if (c < 7) { stage((c + 1) & 1, c + 1); cp_wait<1>(); }
        else       { cp_wait<0>(); }
        __syncthreads();

        const float* pa = sA + (c & 1) * 64 * PAD + m0 * PAD;
        const float* pb = sB + (c & 1) * 64 * PAD + n0 * PAD;
#pragma unroll
        for (int ks = 0; ks < KCH / 8; ++ks) {
            const int kb = ks * 8;
            const unsigned a0 = f2tf32(pa[ g      * PAD + kb + ctig    ]);
            const unsigned a1 = f2tf32(pa[(g + 8) * PAD + kb + ctig    ]);
            const unsigned a2 = f2tf32(pa[ g      * PAD + kb + ctig + 4]);
            const unsigned a3 = f2tf32(pa[(g + 8) * PAD + kb + ctig + 4]);
#pragma unroll
            for (int nb = 0; nb < 4; ++nb) {
                const unsigned b0 = __float_as_uint(pb[(nb * 8 + g) * PAD + kb + ctig    ]);
                const unsigned b1 = __float_as_uint(pb[(nb * 8 + g) * PAD + kb + ctig + 4]);
                mma_tf32(acc[nb][0], acc[nb][1], acc[nb][2], acc[nb][3],
                         a0, a1, a2, a3, b0, b1);
            }
        }
        __syncthreads();
    }

    // writeback: rows r0+m0+g (c0,c1) and r0+m0+g+8 (c2,c3); cols n0+nb*8+2ctig(+1)
#pragma unroll
    for (int nb = 0; nb < 4; ++nb) {
        const int col = n0 + nb * 8 + 2 * ctig;
        const int row1 = r0 + m0 + g;
        const int row2 = row1 + 8;
        if (mode == 0) {
            if (row1 < N_NODES)
                *reinterpret_cast<float2*>(out + (size_t)row1 * 256 + col) =
                    make_float2(acc[nb][0], acc[nb][1]);
            if (row2 < N_NODES)
                *reinterpret_cast<float2*>(out + (size_t)row2 * 256 + col) =
                    make_float2(acc[nb][2], acc[nb][3]);
        } else {
            if (row1 < 3 * N_NODES) {
                const int n = row1 / 3, cc = row1 - 3 * (row1 / 3);
                float* o = out + (size_t)n * 256 + 64 + cc;
                o[3 * col] = acc[nb][0];
                o[3 * (col + 1)] = acc[nb][1];
            }
            if (row2 < 3 * N_NODES) {
                const int n = row2 / 3, cc = row2 - 3 * (row2 / 3);
                float* o = out + (size_t)n * 256 + 64 + cc;
                o[3 * col] = acc[nb][2];
                o[3 * (col + 1)] = acc[nb][3];
            }
        }
    }
}

// ---------------------------------------------------------------------------
extern "C" void kernel_launch(void* const* d_in, const int* /*in_sizes*/, int /*n_in*/,
                              void* d_out, int /*out_size*/)
{
    const float* node_feat  = (const float*)d_in[0];
    const float* node_attr  = (const float*)d_in[1];
    const float* edge_sh    = (const float*)d_in[2];
    const float* edge_basis = (const float*)d_in[3];
    const float* W1s        = (const float*)d_in[4];
    const float* W1v        = (const float*)d_in[5];
    const float* Wfc1       = (const float*)d_in[6];
    const float* Wfc2       = (const float*)d_in[7];
    const float* W2s        = (const float*)d_in[8];
    const float* W2v        = (const float*)d_in[9];
    const float* Wsc_s      = (const float*)d_in[10];
    const float* Wsc_v      = (const float*)d_in[11];
    const int*   edge_idx   = (const int*)d_in[12];
    float* out = (float*)d_out;

    cudaFuncSetAttribute(edge_kernel, cudaFuncAttributeMaxDynamicSharedMemorySize, EDGE_SMEM);
    cudaFuncSetAttribute(out_gemm_tc, cudaFuncAttributeMaxDynamicSharedMemorySize, GEMM_SMEM);

    wfold_kernel<<<160, 256>>>(W2s, Wsc_s, W2v, Wsc_v);
    nodeprep_kernel<<<296, 256>>>(node_feat, node_attr, W1s, W1v);
    edge_kernel<<<296, 256, EDGE_SMEM>>>(edge_sh, edge_basis, Wfc1, Wfc2, edge_idx);

    out_gemm_tc<<<TILES_S + TILES_V, 256, GEMM_SMEM>>>(out);
}

// round 13
// speedup vs baseline: 1.6957x; 1.0026x over previous
#include <cuda_runtime.h>
#include <cstdint>
#include <cstddef>

#define N_NODES 20000
#define N_EDGES 320000
#define EPB 16

#define LOG2_C       0.6931471805599453f
#define INV_SQRT3_C  0.5773502691896258f
#define INV_SQRT8_C  0.35355339059327373f
#define W_SCALE      0.125f
#define INV_MUL_C    0.125f
#define SC_A_C       0.02209708691207961f   // 1/sqrt(128) * 1/sqrt(16)
#define SC_B_C       0.04419417382415922f   // 1/sqrt(512)

#define ROWS_S 20032
#define ROWS_V 60032
#define TILES_S 313
#define TILES_V 938

// scratch (__device__ globals). Referenced ONLY from device code.
__device__ __align__(1024) float d_sv[(size_t)N_NODES * 256];
__device__ __align__(1024) float d_cat_s[(size_t)ROWS_S * 640];
__device__ __align__(1024) float d_cat_v[(size_t)ROWS_V * 640];
__device__ __align__(1024) float d_WcatT_s[64 * 640];   // n-major, tf32 bits
__device__ __align__(1024) float d_WcatT_v[64 * 640];   // n-major, tf32 bits

__device__ __forceinline__ unsigned smem_u32(const void* p) {
    return (unsigned)__cvta_generic_to_shared(p);
}
__device__ __forceinline__ float4 ld4s(const float* p) {
    return *reinterpret_cast<const float4*>(p);
}
__device__ __forceinline__ void cp_async16(unsigned saddr, const void* gaddr) {
    asm volatile("cp.async.cg.shared.global [%0], [%1], 16;" :: "r"(saddr), "l"(gaddr));
}
__device__ __forceinline__ void cp_commit() {
    asm volatile("cp.async.commit_group;" ::: "memory");
}
template<int NWAIT>
__device__ __forceinline__ void cp_wait() {
    asm volatile("cp.async.wait_group %0;" :: "n"(NWAIT) : "memory");
}

// ---- tf32 helpers ------------------------------------------------------
__device__ __forceinline__ unsigned f2tf32(float f) {
    unsigned r;
    asm("cvt.rna.tf32.f32 %0, %1;" : "=r"(r) : "f"(f));
    return r;
}
__device__ __forceinline__ void mma_tf32(float& c0, float& c1, float& c2, float& c3,
                                         unsigned a0, unsigned a1, unsigned a2, unsigned a3,
                                         unsigned b0, unsigned b1) {
    asm volatile(
        "mma.sync.aligned.m16n8k8.row.col.f32.tf32.tf32.f32 "
        "{%0,%1,%2,%3}, {%4,%5,%6,%7}, {%8,%9}, {%0,%1,%2,%3};"
        : "+f"(c0), "+f"(c1), "+f"(c2), "+f"(c3)
        : "r"(a0), "r"(a1), "r"(a2), "r"(a3), "r"(b0), "r"(b1));
}

// ---- log1p(t) on t in [0,1]: degree-7 Chebyshev poly (err ~2e-7) --------
// ln(1+t) = P(u), u = 2t-1.  MUFU-free.
__device__ __forceinline__ float log1p_poly(float t) {
    const float u = fmaf(2.f, t, -1.f);
    float p = 0.0000800429f;
    p = fmaf(p, u, -0.000272121f);
    p = fmaf(p, u,  0.000811464f);
    p = fmaf(p, u, -0.00305802f);
    p = fmaf(p, u,  0.01234897f);
    p = fmaf(p, u, -0.05556137f);
    p = fmaf(p, u,  0.33333319f);
    p = fmaf(p, u,  0.4054653f);
    return p;
}

// ---------------------------------------------------------------------------
// wfold: WcatT[n][k] = tf32( scale * W[k][n] ), n-major with scales folded
// ---------------------------------------------------------------------------
__global__ void wfold_kernel(const float* __restrict__ W2s, const float* __restrict__ Wsc_s,
                             const float* __restrict__ W2v, const float* __restrict__ Wsc_v)
{
    const int i = blockIdx.x * blockDim.x + threadIdx.x;   // over 40960
    if (i >= 40960) return;
    const int n = i / 640, k = i - n * 640;
    const float vs = (k < 128) ? W2s[k * 64 + n] * SC_A_C : Wsc_s[(k - 128) * 64 + n] * SC_B_C;
    const float vv = (k < 128) ? W2v[k * 64 + n] * SC_A_C : Wsc_v[(k - 128) * 64 + n] * SC_B_C;
    d_WcatT_s[i] = __uint_as_float(f2tf32(vs));
    d_WcatT_v[i] = __uint_as_float(f2tf32(vv));
}

// ---------------------------------------------------------------------------
// node prep (unchanged)
// ---------------------------------------------------------------------------
__global__ void __launch_bounds__(256)
nodeprep_kernel(const float* __restrict__ node_feat,
                const float* __restrict__ node_attr,
                const float* __restrict__ W1s,
                const float* __restrict__ W1v)
{
    __shared__ float sW1s[4096];
    __shared__ float sW1v[4096];
    __shared__ float sNF[4][256];
    __shared__ float4 sAT[4][2];

    const int tid = threadIdx.x;
    for (int i = tid; i < 4096; i += 256) { sW1s[i] = W1s[i]; sW1v[i] = W1v[i]; }
    __syncthreads();

    const int ngroups = N_NODES / 4;
    for (int g = blockIdx.x; g < ngroups; g += gridDim.x) {
        const int n0 = g * 4;
        __syncthreads();
        for (int i = tid; i < 1024; i += 256) {
            const int nl = i >> 8, j = i & 255;
            sNF[nl][j] = node_feat[(size_t)(n0 + nl) * 256 + j];
        }
        if (tid < 8) {
            const int nl = tid >> 1, j = tid & 1;
            sAT[nl][j] = __ldg(reinterpret_cast<const float4*>(node_attr + (size_t)(n0 + nl) * 8) + j);
        }
        __syncthreads();

        {
            const int nl = tid >> 6, w = tid & 63;
            const int n = n0 + nl;
            float sacc = 0.f, v0a = 0.f, v1a = 0.f, v2a = 0.f;
#pragma unroll
            for (int u = 0; u < 64; ++u) {
                const float ws = sW1s[u * 64 + w];
                const float wvv = sW1v[u * 64 + w];
                sacc = fmaf(sNF[nl][u], ws, sacc);
                v0a  = fmaf(sNF[nl][64 + 3 * u + 0], wvv, v0a);
                v1a  = fmaf(sNF[nl][64 + 3 * u + 1], wvv, v1a);
                v2a  = fmaf(sNF[nl][64 + 3 * u + 2], wvv, v2a);
            }
            float* o = d_sv + (size_t)n * 256;
            o[w] = sacc * INV_MUL_C;
            o[64 + 3 * w + 0] = v0a * INV_MUL_C;
            o[64 + 3 * w + 1] = v1a * INV_MUL_C;
            o[64 + 3 * w + 2] = v2a * INV_MUL_C;
        }

        if (tid < 128) {
            const int nl = tid >> 5, u = tid & 31;
            reinterpret_cast<float4*>(d_cat_s + (size_t)(n0 + nl) * 640)[u] =
                make_float4(0.f, 0.f, 0.f, 0.f);
        }
        for (int i = tid; i < 384; i += 256) {
            const int rr = i >> 5, u = i & 31;
            const int nl = rr / 3, c = rr - 3 * nl;
            reinterpret_cast<float4*>(d_cat_v + ((size_t)(n0 + nl) * 3 + c) * 640)[u] =
                make_float4(0.f, 0.f, 0.f, 0.f);
        }

        for (int i = tid; i < 512; i += 256) {
            const int nl = i >> 7, p4 = i & 127;
            const float a = sNF[nl][p4 >> 1];
            const float4 at = sAT[nl][p4 & 1];
            reinterpret_cast<float4*>(d_cat_s + (size_t)(n0 + nl) * 640 + 128)[p4] =
                make_float4(a * at.x, a * at.y, a * at.z, a * at.w);
        }
        for (int i = tid; i < 1536; i += 256) {
            const int nl = i / 384;
            const int r  = i - nl * 384;
            const int c  = r >> 7, p4 = r & 127;
            const float a = sNF[nl][64 + 3 * (p4 >> 1) + c];
            const float4 at = sAT[nl][p4 & 1];
            reinterpret_cast<float4*>(d_cat_v + ((size_t)(n0 + nl) * 3 + c) * 640 + 128)[p4] =
                make_float4(a * at.x, a * at.y, a * at.z, a * at.w);
        }
    }
}

// ---------------------------------------------------------------------------
// edge kernel: tf32 mma FC2, EPB=16, prefetch; softplus now 1 MUFU + poly.
// ---------------------------------------------------------------------------
#define SOUT_STRIDE 516
#define EDGE_SMEM (18560 * 4)

__global__ void __launch_bounds__(256, 2)
edge_kernel(const float* __restrict__ edge_sh,
            const float* __restrict__ edge_basis,
            const float* __restrict__ Wfc1,
            const float* __restrict__ Wfc2,
            const int*   __restrict__ edge_idx)
{
    extern __shared__ float esm[];
    float*    sOut  = esm;
    float*    sH    = esm + 16512;
    unsigned* sHu   = reinterpret_cast<unsigned*>(sH);
    float*    sWfc1 = esm + 17600;
    float*    sBas  = esm + 18112;
    float*    sShs  = esm + 18368;
    int*      sIdx  = (int*)(esm + 18496);

    const int tid  = threadIdx.x;
    const int lane = tid & 31, warp = tid >> 5;
    const int g    = lane >> 2;
    const int ctig = lane & 3;
    const int n0   = warp * 32;
    const int region = warp >> 1;

    unsigned bfrag[8][4][2];
#pragma unroll
    for (int ks = 0; ks < 8; ++ks)
#pragma unroll
        for (int nb = 0; nb < 4; ++nb) {
            const int nn = n0 + nb * 8 + g;
            bfrag[ks][nb][0] = f2tf32(Wfc2[(ks * 8 + ctig    ) * 256 + nn] * W_SCALE);
            bfrag[ks][nb][1] = f2tf32(Wfc2[(ks * 8 + ctig + 4) * 256 + nn] * W_SCALE);
        }
    for (int i = tid; i < 512; i += 256) sWfc1[i] = Wfc1[i] * INV_SQRT8_C;

    const int niter = N_EDGES / EPB;

    auto prefetch = [&](int buf, int it_tgt) {
        const size_t e0 = (size_t)it_tgt * EPB;
        if (tid < 32) {
            cp_async16(smem_u32(sBas + buf * 128 + tid * 4), edge_basis + e0 * 8 + tid * 4);
        } else if (tid < 48) {
            cp_async16(smem_u32(sShs + buf * 64 + (tid - 32) * 4), edge_sh + e0 * 4 + (tid - 32) * 4);
        } else if (tid < 56) {
            cp_async16(smem_u32(sIdx + buf * 32 + (tid - 48) * 4), edge_idx + e0 * 2 + (tid - 48) * 4);
        }
    };

    if (tid < 56) { prefetch(0, blockIdx.x); cp_commit(); cp_wait<0>(); }
    __syncthreads();

    int li = 0;
    for (int it = blockIdx.x; it < niter; it += gridDim.x, ++li) {
        const int cur = li & 1;

        if (tid < 4 * EPB) asm volatile("cp.async.bulk.wait_group 1;" ::: "memory");

        {
            const int nit = it + gridDim.x;
            if (tid < 56) {
                if (nit < niter) prefetch(cur ^ 1, nit);
                cp_commit();
            }
        }

        // phase A: h for 16 edges; ssp = max(x,0) + log1p_poly(exp(-|x|)) - ln2
#pragma unroll
        for (int i = tid; i < EPB * 64; i += 256) {
            const int el = i >> 6, k = i & 63;
            const float* bb = sBas + cur * 128 + el * 8;
            const float4 b0 = ld4s(bb);
            const float4 b1 = ld4s(bb + 4);
            float acc;
            acc = b0.x * sWfc1[0 * 64 + k];
            acc = fmaf(b0.y, sWfc1[1 * 64 + k], acc);
            acc = fmaf(b0.z, sWfc1[2 * 64 + k], acc);
            acc = fmaf(b0.w, sWfc1[3 * 64 + k], acc);
            acc = fmaf(b1.x, sWfc1[4 * 64 + k], acc);
            acc = fmaf(b1.y, sWfc1[5 * 64 + k], acc);
            acc = fmaf(b1.z, sWfc1[6 * 64 + k], acc);
            acc = fmaf(b1.w, sWfc1[7 * 64 + k], acc);
            const float t = __expf(-fabsf(acc));          // 1 MUFU
            const float h = fmaxf(acc, 0.f) + log1p_poly(t) - LOG2_C;
            sHu[el * 68 + k] = f2tf32(h);
        }
        __syncthreads();

        float acc[4][4];
#pragma unroll
        for (int nb = 0; nb < 4; ++nb)
#pragma unroll
            for (int j = 0; j < 4; ++j) acc[nb][j] = 0.f;

#pragma unroll
        for (int ks = 0; ks < 8; ++ks) {
            const unsigned a0 = sHu[ g      * 68 + ks * 8 + ctig    ];
            const unsigned a1 = sHu[(g + 8) * 68 + ks * 8 + ctig    ];
            const unsigned a2 = sHu[ g      * 68 + ks * 8 + ctig + 4];
            const unsigned a3 = sHu[(g + 8) * 68 + ks * 8 + ctig + 4];
#pragma unroll
            for (int nb = 0; nb < 4; ++nb)
                mma_tf32(acc[nb][0], acc[nb][1], acc[nb][2], acc[nb][3],
                         a0, a1, a2, a3, bfrag[ks][nb][0], bfrag[ks][nb][1]);
        }

        auto process = [&](float w, int q, int col) {
            const int src = sIdx[cur * 32 + 2 * q + 1];
            const float* nrow = d_sv + (size_t)src * 256;
            const float4 sh = *reinterpret_cast<const float4*>(sShs + cur * 64 + 4 * q);
            float* st = sOut + (cur * EPB + q) * SOUT_STRIDE;
            if (region == 0) {
                st[col] = w * nrow[col] * sh.x;
            } else if (region == 1) {
                const int u = col - 64;
                const float b = w * nrow[u];
                st[128 + u] = b * sh.y;
                st[256 + u] = b * sh.z;
                st[384 + u] = b * sh.w;
            } else if (region == 2) {
                const int u = col - 128;
                const float ws = w * sh.x;
                st[128 + 64 + u] = ws * nrow[64 + 3 * u + 0];
                st[256 + 64 + u] = ws * nrow[64 + 3 * u + 1];
                st[384 + 64 + u] = ws * nrow[64 + 3 * u + 2];
            } else {
                const int u = col - 192;
                const float x0 = nrow[64 + 3 * u + 0];
                const float x1 = nrow[64 + 3 * u + 1];
                const float x2 = nrow[64 + 3 * u + 2];
                st[64 + u] = w * INV_SQRT3_C * (x0 * sh.y + x1 * sh.z + x2 * sh.w);
            }
        };
#pragma unroll
        for (int nb = 0; nb < 4; ++nb) {
            const int colb = n0 + nb * 8 + 2 * ctig;
            process(acc[nb][0], g,     colb);
            process(acc[nb][1], g,     colb + 1);
            process(acc[nb][2], g + 8, colb);
            process(acc[nb][3], g + 8, colb + 1);
        }

        if (tid < 56) cp_wait<0>();
        __syncthreads();

        if (tid < 4 * EPB) {
            asm volatile("fence.proxy.async.shared::cta;" ::: "memory");
            const int q = tid >> 2, part = tid & 3;
            const int dst = sIdx[cur * 32 + 2 * q];
            float* gp = (part == 0)
                      ? (d_cat_s + (size_t)dst * 640)
                      : (d_cat_v + ((size_t)dst * 3 + (part - 1)) * 640);
            const unsigned saddr = smem_u32(sOut + (cur * EPB + q) * SOUT_STRIDE + part * 128);
            asm volatile(
                "cp.reduce.async.bulk.global.shared::cta.bulk_group.add.f32 [%0], [%1], %2;"
                :: "l"(gp), "r"(saddr), "n"(512) : "memory");
            asm volatile("cp.async.bulk.commit_group;" ::: "memory");
        }
    }
    if (tid < 4 * EPB) asm volatile("cp.async.bulk.wait_group 0;" ::: "memory");
}

// ===========================================================================
// Unified tf32 tensor-core out-GEMM (unchanged from R12)
// ===========================================================================
#define KCH 80
#define PAD 84
#define GEMM_SMEM (4 * 64 * PAD * 4)

__global__ void __launch_bounds__(256, 2)
out_gemm_tc(float* __restrict__ out)
{
    const int bid  = blockIdx.x;
    const int mode = (bid >= TILES_S);
    const int tile = mode ? bid - TILES_S : bid;
    const float* __restrict__ A  = mode ? d_cat_v   : d_cat_s;
    const float* __restrict__ Bt = mode ? d_WcatT_v : d_WcatT_s;

    extern __shared__ float sm[];
    float* sA = sm;
    float* sB = sm + 2 * 64 * PAD;

    const int tid = threadIdx.x;
    const int lane = tid & 31, warp = tid >> 5;
    const int g = lane >> 2, ctig = lane & 3;
    const int m0 = (warp & 3) * 16;
    const int n0 = (warp >> 2) * 32;
    const int r0 = tile * 64;

    auto stage = [&](int buf, int c) {
        const int k0 = c * KCH;
        float* sAb = sA + buf * 64 * PAD;
        float* sBb = sB + buf * 64 * PAD;
#pragma unroll
        for (int j = 0; j < 5; ++j) {
            const int idx = tid + 256 * j;
            const int row = idx / 20, u = idx - row * 20;
            cp_async16(smem_u32(sAb + row * PAD + 4 * u),
                       A + (size_t)(r0 + row) * 640 + k0 + 4 * u);
            cp_async16(smem_u32(sBb + row * PAD + 4 * u),
                       Bt + (size_t)row * 640 + k0 + 4 * u);
        }
        cp_commit();
    };

    float acc[4][4];
#pragma unroll
    for (int nb = 0; nb < 4; ++nb)
#pragma unroll
        for (int j = 0; j < 4; ++j) acc[nb][j] = 0.f;

    stage(0, 0);

#pragma unroll 1
    for (int c = 0; c < 8; ++c) {
        if (c < 7) { stage((c + 1) & 1, c + 1); cp_wait<1>(); }
        else       { cp_wait<0>(); }
        __syncthreads();

        const float* pa = sA + (c & 1) * 64 * PAD + m0 * PAD;
        const float* pb = sB + (c & 1) * 64 * PAD + n0 * PAD;
#pragma unroll
        for (int ks = 0; ks < KCH / 8; ++ks) {
            const int kb = ks * 8;
            const unsigned a0 = f2tf32(pa[ g      * PAD + kb + ctig    ]);
            const unsigned a1 = f2tf32(pa[(g + 8) * PAD + kb + ctig    ]);
            const unsigned a2 = f2tf32(pa[ g      * PAD + kb + ctig + 4]);
            const unsigned a3 = f2tf32(pa[(g + 8) * PAD + kb + ctig + 4]);
#pragma unroll
            for (int nb = 0; nb < 4; ++nb) {
                const unsigned b0 = __float_as_uint(pb[(nb * 8 + g) * PAD + kb + ctig    ]);
                const unsigned b1 = __float_as_uint(pb[(nb * 8 + g) * PAD + kb + ctig + 4]);
                mma_tf32(acc[nb][0], acc[nb][1], acc[nb][2], acc[nb][3],
                         a0, a1, a2, a3, b0, b1);
            }
        }
        __syncthreads();
    }

#pragma unroll
    for (int nb = 0; nb < 4; ++nb) {
        const int col = n0 + nb * 8 + 2 * ctig;
        const int row1 = r0 + m0 + g;
        const int row2 = row1 + 8;
        if (mode == 0) {
            if (row1 < N_NODES)
                *reinterpret_cast<float2*>(out + (size_t)row1 * 256 + col) =
                    make_float2(acc[nb][0], acc[nb][1]);
            if (row2 < N_NODES)
                *reinterpret_cast<float2*>(out + (size_t)row2 * 256 + col) =
                    make_float2(acc[nb][2], acc[nb][3]);
        } else {
            if (row1 < 3 * N_NODES) {
                const int n = row1 / 3, cc = row1 - 3 * (row1 / 3);
                float* o = out + (size_t)n * 256 + 64 + cc;
                o[3 * col] = acc[nb][0];
                o[3 * (col + 1)] = acc[nb][1];
            }
            if (row2 < 3 * N_NODES) {
                const int n = row2 / 3, cc = row2 - 3 * (row2 / 3);
                float* o = out + (size_t)n * 256 + 64 + cc;
                o[3 * col] = acc[nb][2];
                o[3 * (col + 1)] = acc[nb][3];
            }
        }
    }
}

// ---------------------------------------------------------------------------
extern "C" void kernel_launch(void* const* d_in, const int* /*in_sizes*/, int /*n_in*/,
                              void* d_out, int /*out_size*/)
{
    const float* node_feat  = (const float*)d_in[0];
    const float* node_attr  = (const float*)d_in[1];
    const float* edge_sh    = (const float*)d_in[2];
    const float* edge_basis = (const float*)d_in[3];
    const float* W1s        = (const float*)d_in[4];
    const float* W1v        = (const float*)d_in[5];
    const float* Wfc1       = (const float*)d_in[6];
    const float* Wfc2       = (const float*)d_in[7];
    const float* W2s        = (const float*)d_in[8];
    const float* W2v        = (const float*)d_in[9];
    const float* Wsc_s      = (const float*)d_in[10];
    const float* Wsc_v      = (const float*)d_in[11];
    const int*   edge_idx   = (const int*)d_in[12];
    float* out = (float*)d_out;

    cudaFuncSetAttribute(edge_kernel, cudaFuncAttributeMaxDynamicSharedMemorySize, EDGE_SMEM);
    cudaFuncSetAttribute(out_gemm_tc, cudaFuncAttributeMaxDynamicSharedMemorySize, GEMM_SMEM);

    wfold_kernel<<<160, 256>>>(W2s, Wsc_s, W2v, Wsc_v);
    nodeprep_kernel<<<296, 256>>>(node_feat, node_attr, W1s, W1v);
    edge_kernel<<<296, 256, EDGE_SMEM>>>(edge_sh, edge_basis, Wfc1, Wfc2, edge_idx);

    out_gemm_tc<<<TILES_S + TILES_V, 256, GEMM_SMEM>>>(out);
}

// round 14
// speedup vs baseline: 2.0650x; 1.2178x over previous
#include <cuda_runtime.h>
#include <cstdint>
#include <cstddef>

#define N_NODES 20000
#define N_EDGES 320000
#define EPB 16

#define LOG2_C       0.6931471805599453f
#define INV_SQRT3_C  0.5773502691896258f
#define INV_SQRT8_C  0.35355339059327373f
#define W_SCALE      0.125f
#define INV_MUL_C    0.125f
#define SC_A_C       0.02209708691207961f   // 1/sqrt(128) * 1/sqrt(16)
#define SC_B_C       0.04419417382415922f   // 1/sqrt(512)

#define ROWS_S 20032
#define ROWS_V 60032
#define TILES_S 313
#define TILES_V 938

// scratch (__device__ globals). Referenced ONLY from device code.
__device__ __align__(1024) float d_sv[(size_t)N_NODES * 256];
__device__ __align__(1024) float d_cat_s[(size_t)ROWS_S * 640];
__device__ __align__(1024) float d_cat_v[(size_t)ROWS_V * 640];
__device__ __align__(1024) float d_WcatT_s[64 * 640];   // n-major, tf32 bits
__device__ __align__(1024) float d_WcatT_v[64 * 640];   // n-major, tf32 bits

__device__ __forceinline__ unsigned smem_u32(const void* p) {
    return (unsigned)__cvta_generic_to_shared(p);
}
__device__ __forceinline__ float4 ld4s(const float* p) {
    return *reinterpret_cast<const float4*>(p);
}
__device__ __forceinline__ void cp_async16(unsigned saddr, const void* gaddr) {
    asm volatile("cp.async.cg.shared.global [%0], [%1], 16;" :: "r"(saddr), "l"(gaddr));
}
__device__ __forceinline__ void cp_commit() {
    asm volatile("cp.async.commit_group;" ::: "memory");
}
template<int NWAIT>
__device__ __forceinline__ void cp_wait() {
    asm volatile("cp.async.wait_group %0;" :: "n"(NWAIT) : "memory");
}

// ---- tf32 helpers ------------------------------------------------------
__device__ __forceinline__ unsigned f2tf32(float f) {
    unsigned r;
    asm("cvt.rna.tf32.f32 %0, %1;" : "=r"(r) : "f"(f));
    return r;
}
__device__ __forceinline__ void mma_tf32(float& c0, float& c1, float& c2, float& c3,
                                         unsigned a0, unsigned a1, unsigned a2, unsigned a3,
                                         unsigned b0, unsigned b1) {
    asm volatile(
        "mma.sync.aligned.m16n8k8.row.col.f32.tf32.tf32.f32 "
        "{%0,%1,%2,%3}, {%4,%5,%6,%7}, {%8,%9}, {%0,%1,%2,%3};"
        : "+f"(c0), "+f"(c1), "+f"(c2), "+f"(c3)
        : "r"(a0), "r"(a1), "r"(a2), "r"(a3), "r"(b0), "r"(b1));
}

// ---- log1p(t) on t in [0,1]: degree-7 Chebyshev poly (err ~2e-7) --------
__device__ __forceinline__ float log1p_poly(float t) {
    const float u = fmaf(2.f, t, -1.f);
    float p = 0.0000800429f;
    p = fmaf(p, u, -0.000272121f);
    p = fmaf(p, u,  0.000811464f);
    p = fmaf(p, u, -0.00305802f);
    p = fmaf(p, u,  0.01234897f);
    p = fmaf(p, u, -0.05556137f);
    p = fmaf(p, u,  0.33333319f);
    p = fmaf(p, u,  0.4054653f);
    return p;
}

// ---------------------------------------------------------------------------
__global__ void wfold_kernel(const float* __restrict__ W2s, const float* __restrict__ Wsc_s,
                             const float* __restrict__ W2v, const float* __restrict__ Wsc_v)
{
    const int i = blockIdx.x * blockDim.x + threadIdx.x;   // over 40960
    if (i >= 40960) return;
    const int n = i / 640, k = i - n * 640;
    const float vs = (k < 128) ? W2s[k * 64 + n] * SC_A_C : Wsc_s[(k - 128) * 64 + n] * SC_B_C;
    const float vv = (k < 128) ? W2v[k * 64 + n] * SC_A_C : Wsc_v[(k - 128) * 64 + n] * SC_B_C;
    d_WcatT_s[i] = __uint_as_float(f2tf32(vs));
    d_WcatT_v[i] = __uint_as_float(f2tf32(vv));
}

// ---------------------------------------------------------------------------
// node prep (unchanged)
// ---------------------------------------------------------------------------
__global__ void __launch_bounds__(256)
nodeprep_kernel(const float* __restrict__ node_feat,
                const float* __restrict__ node_attr,
                const float* __restrict__ W1s,
                const float* __restrict__ W1v)
{
    __shared__ float sW1s[4096];
    __shared__ float sW1v[4096];
    __shared__ float sNF[4][256];
    __shared__ float4 sAT[4][2];

    const int tid = threadIdx.x;
    for (int i = tid; i < 4096; i += 256) { sW1s[i] = W1s[i]; sW1v[i] = W1v[i]; }
    __syncthreads();

    const int ngroups = N_NODES / 4;
    for (int g = blockIdx.x; g < ngroups; g += gridDim.x) {
        const int n0 = g * 4;
        __syncthreads();
        for (int i = tid; i < 1024; i += 256) {
            const int nl = i >> 8, j = i & 255;
            sNF[nl][j] = node_feat[(size_t)(n0 + nl) * 256 + j];
        }
        if (tid < 8) {
            const int nl = tid >> 1, j = tid & 1;
            sAT[nl][j] = __ldg(reinterpret_cast<const float4*>(node_attr + (size_t)(n0 + nl) * 8) + j);
        }
        __syncthreads();

        {
            const int nl = tid >> 6, w = tid & 63;
            const int n = n0 + nl;
            float sacc = 0.f, v0a = 0.f, v1a = 0.f, v2a = 0.f;
#pragma unroll
            for (int u = 0; u < 64; ++u) {
                const float ws = sW1s[u * 64 + w];
                const float wvv = sW1v[u * 64 + w];
                sacc = fmaf(sNF[nl][u], ws, sacc);
                v0a  = fmaf(sNF[nl][64 + 3 * u + 0], wvv, v0a);
                v1a  = fmaf(sNF[nl][64 + 3 * u + 1], wvv, v1a);
                v2a  = fmaf(sNF[nl][64 + 3 * u + 2], wvv, v2a);
            }
            float* o = d_sv + (size_t)n * 256;
            o[w] = sacc * INV_MUL_C;
            o[64 + 3 * w + 0] = v0a * INV_MUL_C;
            o[64 + 3 * w + 1] = v1a * INV_MUL_C;
            o[64 + 3 * w + 2] = v2a * INV_MUL_C;
        }

        if (tid < 128) {
            const int nl = tid >> 5, u = tid & 31;
            reinterpret_cast<float4*>(d_cat_s + (size_t)(n0 + nl) * 640)[u] =
                make_float4(0.f, 0.f, 0.f, 0.f);
        }
        for (int i = tid; i < 384; i += 256) {
            const int rr = i >> 5, u = i & 31;
            const int nl = rr / 3, c = rr - 3 * nl;
            reinterpret_cast<float4*>(d_cat_v + ((size_t)(n0 + nl) * 3 + c) * 640)[u] =
                make_float4(0.f, 0.f, 0.f, 0.f);
        }

        for (int i = tid; i < 512; i += 256) {
            const int nl = i >> 7, p4 = i & 127;
            const float a = sNF[nl][p4 >> 1];
            const float4 at = sAT[nl][p4 & 1];
            reinterpret_cast<float4*>(d_cat_s + (size_t)(n0 + nl) * 640 + 128)[p4] =
                make_float4(a * at.x, a * at.y, a * at.z, a * at.w);
        }
        for (int i = tid; i < 1536; i += 256) {
            const int nl = i / 384;
            const int r  = i - nl * 384;
            const int c  = r >> 7, p4 = r & 127;
            const float a = sNF[nl][64 + 3 * (p4 >> 1) + c];
            const float4 at = sAT[nl][p4 & 1];
            reinterpret_cast<float4*>(d_cat_v + ((size_t)(n0 + nl) * 3 + c) * 640 + 128)[p4] =
                make_float4(a * at.x, a * at.y, a * at.z, a * at.w);
        }
    }
}

// ---------------------------------------------------------------------------
// edge kernel v5: tf32 mma FC2 + cp.async-prefetched NODE-ROW GATHER.
// Pipeline per iteration i:
//   top   : bulk-wait(sOut), issue bundle prefetch i+1
//   phaseA: h (from sBas[cur])
//   mid   : cp.async wait (gather for i, committed end of i-1), barrier
//   phaseB: tensor-core FC2
//   phaseC: tensor product reading gathered rows from SMEM (LDS, not LDG)
//   tail  : bundle wait, barrier, bulk reduces, issue gather i+1, commit
// Group FIFO: tid<56 = [gather, bundle] -> mid wait<1>, tail wait<0>;
//             tid>=56 = [gather]        -> mid wait<0>.
// smem (floats):
//   sOut [0,16512)      2*16*516
//   sGat [16512,24832)  2*16*260
//   sH   [24832,25920)  16*68
//   sWfc1[25920,26432)  512
//   sBas [26432,26688)  256
//   sShs [26688,26816)  128
//   sIdx [26816,26880)  64
// total 26880 floats = 107520 B -> 2 CTAs/SM
// ---------------------------------------------------------------------------
#define SOUT_STRIDE 516
#define GAT_STRIDE 260
#define EDGE_SMEM (26880 * 4)

__global__ void __launch_bounds__(256, 2)
edge_kernel(const float* __restrict__ edge_sh,
            const float* __restrict__ edge_basis,
            const float* __restrict__ Wfc1,
            const float* __restrict__ Wfc2,
            const int*   __restrict__ edge_idx)
{
    extern __shared__ float esm[];
    float*    sOut  = esm;
    float*    sGat  = esm + 16512;
    float*    sH    = esm + 24832;
    unsigned* sHu   = reinterpret_cast<unsigned*>(sH);
    float*    sWfc1 = esm + 25920;
    float*    sBas  = esm + 26432;
    float*    sShs  = esm + 26688;
    int*      sIdx  = (int*)(esm + 26816);

    const int tid  = threadIdx.x;
    const int lane = tid & 31, warp = tid >> 5;
    const int g    = lane >> 2;
    const int ctig = lane & 3;
    const int n0   = warp * 32;
    const int region = warp >> 1;

    unsigned bfrag[8][4][2];
#pragma unroll
    for (int ks = 0; ks < 8; ++ks)
#pragma unroll
        for (int nb = 0; nb < 4; ++nb) {
            const int nn = n0 + nb * 8 + g;
            bfrag[ks][nb][0] = f2tf32(Wfc2[(ks * 8 + ctig    ) * 256 + nn] * W_SCALE);
            bfrag[ks][nb][1] = f2tf32(Wfc2[(ks * 8 + ctig + 4) * 256 + nn] * W_SCALE);
        }
    for (int i = tid; i < 512; i += 256) sWfc1[i] = Wfc1[i] * INV_SQRT8_C;

    const int niter = N_EDGES / EPB;

    auto prefetch = [&](int buf, int it_tgt) {
        const size_t e0 = (size_t)it_tgt * EPB;
        if (tid < 32) {
            cp_async16(smem_u32(sBas + buf * 128 + tid * 4), edge_basis + e0 * 8 + tid * 4);
        } else if (tid < 48) {
            cp_async16(smem_u32(sShs + buf * 64 + (tid - 32) * 4), edge_sh + e0 * 4 + (tid - 32) * 4);
        } else if (tid < 56) {
            cp_async16(smem_u32(sIdx + buf * 32 + (tid - 48) * 4), edge_idx + e0 * 2 + (tid - 48) * 4);
        }
    };

    // gather the 16 src rows for buffer gbuf using indices in sIdx[ibuf]
    auto gather_issue = [&](int gbuf, int ibuf, bool valid) {
        if (valid) {
#pragma unroll
            for (int j = 0; j < 4; ++j) {
                const int c = tid + 256 * j;        // 0..1023
                const int row = c >> 6;              // edge 0..15
                const int off = (c & 63) * 4;        // float offset in row
                const int src = sIdx[ibuf * 32 + 2 * row + 1];
                cp_async16(smem_u32(sGat + (gbuf * 16 + row) * GAT_STRIDE + off),
                           d_sv + (size_t)src * 256 + off);
            }
        }
        cp_commit();
    };

    // prologue: bundle(it0) -> wait -> gather(it0)
    if (tid < 56) { prefetch(0, blockIdx.x); cp_commit(); cp_wait<0>(); }
    __syncthreads();
    gather_issue(0, 0, blockIdx.x < niter);

    int li = 0;
    for (int it = blockIdx.x; it < niter; it += gridDim.x, ++li) {
        const int cur = li & 1;
        const int nit = it + gridDim.x;

        if (tid < 4 * EPB) asm volatile("cp.async.bulk.wait_group 1;" ::: "memory");

        if (tid < 56) {
            if (nit < niter) prefetch(cur ^ 1, nit);
            cp_commit();
        }

        // phase A: h for 16 edges
#pragma unroll
        for (int i = tid; i < EPB * 64; i += 256) {
            const int el = i >> 6, k = i & 63;
            const float* bb = sBas + cur * 128 + el * 8;
            const float4 b0 = ld4s(bb);
            const float4 b1 = ld4s(bb + 4);
            float acc;
            acc = b0.x * sWfc1[0 * 64 + k];
            acc = fmaf(b0.y, sWfc1[1 * 64 + k], acc);
            acc = fmaf(b0.z, sWfc1[2 * 64 + k], acc);
            acc = fmaf(b0.w, sWfc1[3 * 64 + k], acc);
            acc = fmaf(b1.x, sWfc1[4 * 64 + k], acc);
            acc = fmaf(b1.y, sWfc1[5 * 64 + k], acc);
            acc = fmaf(b1.z, sWfc1[6 * 64 + k], acc);
            acc = fmaf(b1.w, sWfc1[7 * 64 + k], acc);
            const float t = __expf(-fabsf(acc));
            const float h = fmaxf(acc, 0.f) + log1p_poly(t) - LOG2_C;
            sHu[el * 68 + k] = f2tf32(h);
        }

        // mid wait: gather for THIS iteration must have landed
        if (tid < 56) cp_wait<1>(); else cp_wait<0>();
        __syncthreads();

        // phase B: tensor-core FC2
        float acc[4][4];
#pragma unroll
        for (int nb = 0; nb < 4; ++nb)
#pragma unroll
            for (int j = 0; j < 4; ++j) acc[nb][j] = 0.f;

#pragma unroll
        for (int ks = 0; ks < 8; ++ks) {
            const unsigned a0 = sHu[ g      * 68 + ks * 8 + ctig    ];
            const unsigned a1 = sHu[(g + 8) * 68 + ks * 8 + ctig    ];
            const unsigned a2 = sHu[ g      * 68 + ks * 8 + ctig + 4];
            const unsigned a3 = sHu[(g + 8) * 68 + ks * 8 + ctig + 4];
#pragma unroll
            for (int nb = 0; nb < 4; ++nb)
                mma_tf32(acc[nb][0], acc[nb][1], acc[nb][2], acc[nb][3],
                         a0, a1, a2, a3, bfrag[ks][nb][0], bfrag[ks][nb][1]);
        }

        // phase C: tensor product from gathered SMEM rows
        auto process = [&](float w, int q, int col) {
            const float* nrow = sGat + (cur * 16 + q) * GAT_STRIDE;
            const float4 sh = *reinterpret_cast<const float4*>(sShs + cur * 64 + 4 * q);
            float* st = sOut + (cur * EPB + q) * SOUT_STRIDE;
            if (region == 0) {
                st[col] = w * nrow[col] * sh.x;
            } else if (region == 1) {
                const int u = col - 64;
                const float b = w * nrow[u];
                st[128 + u] = b * sh.y;
                st[256 + u] = b * sh.z;
                st[384 + u] = b * sh.w;
            } else if (region == 2) {
                const int u = col - 128;
                const float ws = w * sh.x;
                st[128 + 64 + u] = ws * nrow[64 + 3 * u + 0];
                st[256 + 64 + u] = ws * nrow[64 + 3 * u + 1];
                st[384 + 64 + u] = ws * nrow[64 + 3 * u + 2];
            } else {
                const int u = col - 192;
                const float x0 = nrow[64 + 3 * u + 0];
                const float x1 = nrow[64 + 3 * u + 1];
                const float x2 = nrow[64 + 3 * u + 2];
                st[64 + u] = w * INV_SQRT3_C * (x0 * sh.y + x1 * sh.z + x2 * sh.w);
            }
        };
#pragma unroll
        for (int nb = 0; nb < 4; ++nb) {
            const int colb = n0 + nb * 8 + 2 * ctig;
            process(acc[nb][0], g,     colb);
            process(acc[nb][1], g,     colb + 1);
            process(acc[nb][2], g + 8, colb);
            process(acc[nb][3], g + 8, colb + 1);
        }

        // tail: bundle for i+1 must have landed (indices needed by gather below)
        if (tid < 56) cp_wait<0>();
        __syncthreads();

        if (tid < 4 * EPB) {
            asm volatile("fence.proxy.async.shared::cta;" ::: "memory");
            const int q = tid >> 2, part = tid & 3;
            const int dst = sIdx[cur * 32 + 2 * q];
            float* gp = (part == 0)
                      ? (d_cat_s + (size_t)dst * 640)
                      : (d_cat_v + ((size_t)dst * 3 + (part - 1)) * 640);
            const unsigned saddr = smem_u32(sOut + (cur * EPB + q) * SOUT_STRIDE + part * 128);
            asm volatile(
                "cp.reduce.async.bulk.global.shared::cta.bulk_group.add.f32 [%0], [%1], %2;"
                :: "l"(gp), "r"(saddr), "n"(512) : "memory");
            asm volatile("cp.async.bulk.commit_group;" ::: "memory");
        }

        // issue gather for the NEXT iteration (indices just validated)
        gather_issue(cur ^ 1, cur ^ 1, nit < niter);
    }
    if (tid < 4 * EPB) asm volatile("cp.async.bulk.wait_group 0;" ::: "memory");
}

// ===========================================================================
// Unified tf32 tensor-core out-GEMM (unchanged from R12)
// ===========================================================================
#define KCH 80
#define PAD 84
#define GEMM_SMEM (4 * 64 * PAD * 4)

__global__ void __launch_bounds__(256, 2)
out_gemm_tc(float* __restrict__ out)
{
    const int bid  = blockIdx.x;
    const int mode = (bid >= TILES_S);
    const int tile = mode ? bid - TILES_S : bid;
    const float* __restrict__ A  = mode ? d_cat_v   : d_cat_s;
    const float* __restrict__ Bt = mode ? d_WcatT_v : d_WcatT_s;

    extern __shared__ float sm[];
    float* sA = sm;
    float* sB = sm + 2 * 64 * PAD;

    const int tid = threadIdx.x;
    const int lane = tid & 31, warp = tid >> 5;
    const int g = lane >> 2, ctig = lane & 3;
    const int m0 = (warp & 3) * 16;
    const int n0 = (warp >> 2) * 32;
    const int r0 = tile * 64;

    auto stage = [&](int buf, int c) {
        const int k0 = c * KCH;
        float* sAb = sA + buf * 64 * PAD;
        float* sBb = sB + buf * 64 * PAD;
#pragma unroll
        for (int j = 0; j < 5; ++j) {
            const int idx = tid + 256 * j;
            const int row = idx / 20, u = idx - row * 20;
            cp_async16(smem_u32(sAb + row * PAD + 4 * u),
                       A + (size_t)(r0 + row) * 640 + k0 + 4 * u);
            cp_async16(smem_u32(sBb + row * PAD + 4 * u),
                       Bt + (size_t)row * 640 + k0 + 4 * u);
        }
        cp_commit();
    };

    float acc[4][4];
#pragma unroll
    for (int nb = 0; nb < 4; ++nb)
#pragma unroll
        for (int j = 0; j < 4; ++j) acc[nb][j] = 0.f;

    stage(0, 0);

#pragma unroll 1
    for (int c = 0; c < 8; ++c) {
        if (c < 7) { stage((c + 1) & 1, c + 1); cp_wait<1>(); }
        else       { cp_wait<0>(); }
        __syncthreads();

        const float* pa = sA + (c & 1) * 64 * PAD + m0 * PAD;
        const float* pb = sB + (c & 1) * 64 * PAD + n0 * PAD;
#pragma unroll
        for (int ks = 0; ks < KCH / 8; ++ks) {
            const int kb = ks * 8;
            const unsigned a0 = f2tf32(pa[ g      * PAD + kb + ctig    ]);
            const unsigned a1 = f2tf32(pa[(g + 8) * PAD + kb + ctig    ]);
            const unsigned a2 = f2tf32(pa[ g      * PAD + kb + ctig + 4]);
            const unsigned a3 = f2tf32(pa[(g + 8) * PAD + kb + ctig + 4]);
#pragma unroll
            for (int nb = 0; nb < 4; ++nb) {
                const unsigned b0 = __float_as_uint(pb[(nb * 8 + g) * PAD + kb + ctig    ]);
                const unsigned b1 = __float_as_uint(pb[(nb * 8 + g) * PAD + kb + ctig + 4]);
                mma_tf32(acc[nb][0], acc[nb][1], acc[nb][2], acc[nb][3],
                         a0, a1, a2, a3, b0, b1);
            }
        }
        __syncthreads();
    }

#pragma unroll
    for (int nb = 0; nb < 4; ++nb) {
        const int col = n0 + nb * 8 + 2 * ctig;
        const int row1 = r0 + m0 + g;
        const int row2 = row1 + 8;
        if (mode == 0) {
            if (row1 < N_NODES)
                *reinterpret_cast<float2*>(out + (size_t)row1 * 256 + col) =
                    make_float2(acc[nb][0], acc[nb][1]);
            if (row2 < N_NODES)
                *reinterpret_cast<float2*>(out + (size_t)row2 * 256 + col) =
                    make_float2(acc[nb][2], acc[nb][3]);
        } else {
            if (row1 < 3 * N_NODES) {
                const int n = row1 / 3, cc = row1 - 3 * (row1 / 3);
                float* o = out + (size_t)n * 256 + 64 + cc;
                o[3 * col] = acc[nb][0];
                o[3 * (col + 1)] = acc[nb][1];
            }
            if (row2 < 3 * N_NODES) {
                const int n = row2 / 3, cc = row2 - 3 * (row2 / 3);
                float* o = out + (size_t)n * 256 + 64 + cc;
                o[3 * col] = acc[nb][2];
                o[3 * (col + 1)] = acc[nb][3];
            }
        }
    }
}

// ---------------------------------------------------------------------------
extern "C" void kernel_launch(void* const* d_in, const int* /*in_sizes*/, int /*n_in*/,
                              void* d_out, int /*out_size*/)
{
    const float* node_feat  = (const float*)d_in[0];
    const float* node_attr  = (const float*)d_in[1];
    const float* edge_sh    = (const float*)d_in[2];
    const float* edge_basis = (const float*)d_in[3];
    const float* W1s        = (const float*)d_in[4];
    const float* W1v        = (const float*)d_in[5];
    const float* Wfc1       = (const float*)d_in[6];
    const float* Wfc2       = (const float*)d_in[7];
    const float* W2s        = (const float*)d_in[8];
    const float* W2v        = (const float*)d_in[9];
    const float* Wsc_s      = (const float*)d_in[10];
    const float* Wsc_v      = (const float*)d_in[11];
    const int*   edge_idx   = (const int*)d_in[12];
    float* out = (float*)d_out;

    cudaFuncSetAttribute(edge_kernel, cudaFuncAttributeMaxDynamicSharedMemorySize, EDGE_SMEM);
    cudaFuncSetAttribute(out_gemm_tc, cudaFuncAttributeMaxDynamicSharedMemorySize, GEMM_SMEM);

    wfold_kernel<<<160, 256>>>(W2s, Wsc_s, W2v, Wsc_v);
    nodeprep_kernel<<<296, 256>>>(node_feat, node_attr, W1s, W1v);
    edge_kernel<<<296, 256, EDGE_SMEM>>>(edge_sh, edge_basis, Wfc1, Wfc2, edge_idx);

    out_gemm_tc<<<TILES_S + TILES_V, 256, GEMM_SMEM>>>(out);
}